// round 10
// baseline (speedup 1.0000x reference)
#include <cuda_runtime.h>
#include <cuda_bf16.h>

// ---------------------------------------------------------------------------
// Problem constants
// ---------------------------------------------------------------------------
#define BATCH   2
#define HF      38
#define WF      50
#define HW      1900          // HF*WF
#define ANUM    9
#define NANCH   17100         // HW*ANUM
#define CIN     1024
#define CMID    512
#define K9      9216          // CIN*9
#define KT      64
#define NKT     (K9 / KT)     // 144
#define MT      64            // conv3 M tile
#define APc     68            // padded A width (64+4)
#define PRE     6000
#define POST    300
#define NW      94            // ceil(PRE/64)
#define NMS_TH  0.7f

// canonical Faster-RCNN base anchors (base=16, ratios .5/1/2, scales 8/16/32)
__constant__ float c_base[9][4] = {
    {-84.f,  -40.f,  99.f,  55.f},
    {-176.f, -88.f, 191.f, 103.f},
    {-360.f,-184.f, 375.f, 199.f},
    {-56.f,  -56.f,  71.f,  71.f},
    {-120.f,-120.f, 135.f, 135.f},
    {-248.f,-248.f, 263.f, 263.f},
    {-36.f,  -80.f,  51.f,  95.f},
    {-80.f, -168.f,  95.f, 183.f},
    {-168.f,-344.f, 183.f, 359.f}
};

// ---------------------------------------------------------------------------
// Scratch (static device allocations; runtime alloc is forbidden)
// ---------------------------------------------------------------------------
__device__ float               g_x    [BATCH * CMID * HW];   // conv3+relu out
__device__ float               g_cls  [BATCH * 18 * HW];
__device__ float               g_reg  [BATCH * 36 * HW];
__device__ unsigned long long  g_keys [BATCH * NANCH];
__device__ float               g_boxes[BATCH * NANCH * 4];
__device__ float               g_tops [BATCH * PRE * 4];
__device__ unsigned long long  g_mask [BATCH * PRE * NW];
__device__ float               g_ov   [BATCH * NANCH * 20];
__device__ int                 g_labels[BATCH * NANCH];
__device__ int                 g_amax [BATCH * NANCH];
__device__ unsigned int        g_gtmax[BATCH * 20];
__device__ float               g_acc  [4];                   // negpick, cnt, reg0, reg1
__device__ int                 g_nex  [BATCH];

// ---------------------------------------------------------------------------
// helpers
// ---------------------------------------------------------------------------
__device__ __forceinline__ unsigned f2u(float f) {
    unsigned u = __float_as_uint(f);
    return (u & 0x80000000u) ? ~u : (u | 0x80000000u);
}
__device__ __forceinline__ float u2f(unsigned u) {
    unsigned bits = (u & 0x80000000u) ? (u & 0x7FFFFFFFu) : ~u;
    return __uint_as_float(bits);
}
__device__ __forceinline__ void anchor_coords(int n, float& ax1, float& ay1,
                                              float& ax2, float& ay2) {
    int p = n / 9, a = n - 9 * p;
    int y = p / WF, x = p - WF * y;
    float sx = 16.f * x, sy = 16.f * y;
    ax1 = c_base[a][0] + sx; ay1 = c_base[a][1] + sy;
    ax2 = c_base[a][2] + sx; ay2 = c_base[a][3] + sy;
}
__device__ __forceinline__ float smooth1(float d) {
    float ad = fabsf(d);
    return (ad < (1.0f / 9.0f)) ? (4.5f * d * d) : (ad - 0.5f / 9.0f);
}

// packed f32x2 ops (bit-identical to two independent scalar IEEE ops)
typedef unsigned long long ull;
#define SGN2 0x8000000080000000ULL
__device__ __forceinline__ ull dup2(float s) {
    ull d; asm("mov.b64 %0, {%1, %1};" : "=l"(d) : "f"(s)); return d;
}
__device__ __forceinline__ ull fma2(ull a, ull b, ull c) {
    ull d; asm("fma.rn.f32x2 %0, %1, %2, %3;" : "=l"(d) : "l"(a), "l"(b), "l"(c));
    return d;
}
__device__ __forceinline__ ull add2(ull a, ull b) {
    ull d; asm("add.rn.f32x2 %0, %1, %2;" : "=l"(d) : "l"(a), "l"(b)); return d;
}
__device__ __forceinline__ ull sub2(ull a, ull b) {   // a + (-b), same rounding as scalar sub
    return add2(a, b ^ SGN2);
}
__device__ __forceinline__ void unpack2(ull v, float& lo, float& hi) {
    asm("mov.b64 {%0, %1}, %2;" : "=f"(lo), "=f"(hi) : "l"(v));
}

// cp.async helpers
__device__ __forceinline__ void cpa4(unsigned dst, const void* src, int srcsz) {
    asm volatile("cp.async.ca.shared.global [%0], [%1], 4, %2;"
                 :: "r"(dst), "l"(src), "r"(srcsz));
}
__device__ __forceinline__ void cpa16(unsigned dst, const void* src) {
    asm volatile("cp.async.cg.shared.global [%0], [%1], 16;"
                 :: "r"(dst), "l"(src));
}
#define CP_COMMIT()   asm volatile("cp.async.commit_group;")
#define CP_WAIT(n)    asm volatile("cp.async.wait_group %0;" :: "n"(n))
#define CP_WAIT_ALL() asm volatile("cp.async.wait_all;")

// ---------------------------------------------------------------------------
// zero-init kernel (accumulators)
// ---------------------------------------------------------------------------
__global__ void init_zero() {
    int t = threadIdx.x;
    if (t < 4)  g_acc[t] = 0.f;
    if (t < BATCH * 20) g_gtmax[t] = 0u;
}

// ---------------------------------------------------------------------------
// conv3x3 1024->512 as implicit-GEMM, 64(M)x128(N) tiles, KT=64, f32x2 FMA,
// Kahan-compensated per-tile merge (registers), cp.async DOUBLE-BUFFERED.
// grid (15, 8, BATCH) = 240 CTAs, block 256, __launch_bounds__(256,2):
// 2 co-resident CTAs per SM hide each other's barrier/copy stalls and
// spread the work over all 148 SMs. Per-output arithmetic identical to the
// 128x128 version (same K order, same Kahan grouping) -> bit-identical out.
// dyn smem per CTA: 2 x A[KT][APc] + 2 x B[KT][128] = 100352 B.
// ---------------------------------------------------------------------------
extern __shared__ unsigned char smem_raw[];

#define C3_A_FLOATS (KT * APc)    // 4352
#define C3_B_FLOATS (KT * 128)    // 8192
#define C3_SMEM_BYTES ((2 * C3_A_FLOATS + 2 * C3_B_FLOATS) * 4)  // 100352

__global__ void __launch_bounds__(256, 2) conv3_gemm(
    const float* __restrict__ feat, const float* __restrict__ wconv,
    const float* __restrict__ bconv)
{
    float* AsBuf = (float*)smem_raw;                 // [2][KT][APc]
    float* BsBuf = AsBuf + 2 * C3_A_FLOATS;          // [2][KT][128]
    const unsigned sA = (unsigned)__cvta_generic_to_shared(AsBuf);
    const unsigned sB = (unsigned)__cvta_generic_to_shared(BsBuf);

    const int b  = blockIdx.z;
    const int m0 = blockIdx.y * MT;
    const int n0 = blockIdx.x * 128;
    const int tid = threadIdx.x;

    ull acc2[16], comp2[16];
    #pragma unroll
    for (int e = 0; e < 16; e++) { acc2[e] = 0ULL; comp2[e] = 0ULL; }

    const int bcol = tid & 127;
    const int p    = n0 + bcol;
    const int py   = p / WF, px = p - WF * (p / WF);
    const bool pvalid = p < HW;
    const float* fb = feat + b * (CIN * HW);

    const int tm = (tid >> 5) << 3;   // warp-uniform: 0..56
    const int tn = (tid & 31) << 2;   // 0..124
    const int krow0 = tid >> 7;       // 0..1

    auto issue_tile = [&](int kt, int buf) {
        // A tile: 64 m x 64 k = 4096 elems, 16 x cp.async 4B per thread
        #pragma unroll
        for (int r = 0; r < 16; r++) {
            int e = tid + 256 * r;
            int row = e >> 6, col = e & 63;
            const float* src = &wconv[(m0 + row) * K9 + kt * KT + col];
            unsigned dst = sA + (unsigned)((buf * KT + col) * APc + row) * 4u;
            cpa4(dst, src, 4);
        }
        // B tile (im2col): 64 k-rows x 128 cols, 32 x cp.async 4B,
        // zero-fill when out of bounds
        #pragma unroll
        for (int r = 0; r < 32; r++) {
            int krow = krow0 + 2 * r;
            int kg = kt * KT + krow;
            int c = kg / 9;
            int t = kg - 9 * c;
            int dy = t / 3 - 1;
            int dx = t - (t / 3) * 3 - 1;
            int yy = py + dy, xx = px + dx;
            bool valid = pvalid && (unsigned)yy < (unsigned)HF && (unsigned)xx < (unsigned)WF;
            const float* src = valid ? &fb[c * HW + yy * WF + xx] : fb;
            unsigned dst = sB + (unsigned)((buf * KT + krow) * 128 + bcol) * 4u;
            cpa4(dst, src, valid ? 4 : 0);
        }
        CP_COMMIT();
    };

    issue_tile(0, 0);
    CP_WAIT(0);
    __syncthreads();

    for (int kt = 0; kt < NKT; kt++) {
        const int cur = kt & 1;
        if (kt + 1 < NKT) issue_tile(kt + 1, cur ^ 1);

        const float* As_cur = AsBuf + cur * C3_A_FLOATS;
        const float* Bs_cur = BsBuf + cur * C3_B_FLOATS;

        ull part2[16];
        #pragma unroll
        for (int e = 0; e < 16; e++) part2[e] = 0ULL;

        #pragma unroll 8
        for (int kk = 0; kk < KT; kk++) {
            const ulonglong2* ap = (const ulonglong2*)&As_cur[kk * APc + tm];
            ulonglong2 a01 = ap[0];
            ulonglong2 a23 = ap[1];
            ull am[4] = {a01.x, a01.y, a23.x, a23.y};
            float4 bq = *(const float4*)&Bs_cur[kk * 128 + tn];
            ull bd[4] = {dup2(bq.x), dup2(bq.y), dup2(bq.z), dup2(bq.w)};
            #pragma unroll
            for (int mp = 0; mp < 4; mp++)
                #pragma unroll
                for (int j = 0; j < 4; j++)
                    part2[mp * 4 + j] = fma2(am[mp], bd[j], part2[mp * 4 + j]);
        }
        // Kahan merge of the 64-product partial into the running sum (f32x2)
        #pragma unroll
        for (int e = 0; e < 16; e++) {
            ull y = sub2(part2[e], comp2[e]);
            ull t = add2(acc2[e], y);
            comp2[e] = sub2(sub2(t, acc2[e]), y);
            acc2[e] = t;
        }
        if (kt + 1 < NKT) CP_WAIT(0);
        __syncthreads();
    }
    #pragma unroll
    for (int mp = 0; mp < 4; mp++) {
        int co0 = m0 + tm + 2 * mp;
        float b0 = bconv[co0], b1 = bconv[co0 + 1];
        #pragma unroll
        for (int j = 0; j < 4; j++) {
            int pp = n0 + tn + j;
            if (pp < HW) {
                float lo, hi;
                unpack2(acc2[mp * 4 + j], lo, hi);
                float v0 = lo + b0, v1 = hi + b1;
                g_x[b * (CMID * HW) + co0 * HW + pp]       = v0 > 0.f ? v0 : 0.f;
                g_x[b * (CMID * HW) + (co0 + 1) * HW + pp] = v1 > 0.f ? v1 : 0.f;
            }
        }
    }
}

// ---------------------------------------------------------------------------
// fused 1x1 convs (cls 18 + reg 36), Kahan accumulation, 8-way K-split.
// grid (60, BATCH), block 256 = 32 positions x 8 K-chunks of 64 channels.
// ALL in dynamic smem: wT [512][54] (110592 B) + partials [32][54][8]
// (55296 B) = 165888 B. Deterministic fixed-order merge (no float atomics).
// ---------------------------------------------------------------------------
#define C1_POS 32
#define C1_KS  8
#define C1_WT_FLOATS (512 * 54)
#define C1_SMEM_BYTES ((C1_WT_FLOATS + C1_POS * 54 * C1_KS) * 4)

__global__ void __launch_bounds__(256) conv1x1(
    const float* __restrict__ wcls, const float* __restrict__ bcls,
    const float* __restrict__ wreg, const float* __restrict__ breg)
{
    float* wT = (float*)smem_raw;                 // [512][54]
    float* sp = wT + C1_WT_FLOATS;                // [32][54][8]
    const int b  = blockIdx.y;
    const int p0 = blockIdx.x * C1_POS;
    const int tid = threadIdx.x;
    const int pos = tid & 31;
    const int ks  = tid >> 5;      // 0..7

    for (int e = tid; e < 512 * 18; e += 256) {
        int o = e / 512, c = e - 512 * o;
        wT[c * 54 + o] = wcls[e];
    }
    for (int e = tid; e < 512 * 36; e += 256) {
        int o = e / 512, c = e - 512 * o;
        wT[c * 54 + 18 + o] = wreg[e];
    }
    __syncthreads();

    const int p = p0 + pos;
    const bool v = p < HW;
    float acc[54], comp[54];
    #pragma unroll
    for (int o = 0; o < 54; o++) { acc[o] = 0.f; comp[o] = 0.f; }

    const float* xb = g_x + b * (CMID * HW) + (v ? p : 0);
    const int c0 = ks * 64;
    for (int c = c0; c < c0 + 64; c++) {
        float xv = v ? xb[c * HW] : 0.f;
        const float* w = &wT[c * 54];
        #pragma unroll
        for (int o = 0; o < 54; o++) {
            float y = __fmaf_rn(xv, w[o], -comp[o]);
            float t = __fadd_rn(acc[o], y);
            comp[o] = __fsub_rn(__fsub_rn(t, acc[o]), y);
            acc[o] = t;
        }
    }
    #pragma unroll
    for (int o = 0; o < 54; o++) sp[(pos * 54 + o) * C1_KS + ks] = acc[o];
    __syncthreads();

    // merge 8 partials per (pos, o) in fixed order -> deterministic
    for (int e = tid; e < C1_POS * 54; e += 256) {
        int pos2 = e / 54, o = e - 54 * pos2;
        int pp = p0 + pos2;
        if (pp >= HW) continue;
        float s = 0.f;
        #pragma unroll
        for (int k = 0; k < C1_KS; k++) s = __fadd_rn(s, sp[(pos2 * 54 + o) * C1_KS + k]);
        if (o < 18) g_cls[b * 18 * HW + o * HW + pp] = s + bcls[o];
        else        g_reg[b * 36 * HW + (o - 18) * HW + pp] = s + breg[o - 18];
    }
}

// ---------------------------------------------------------------------------
// proposal prep: decode boxes, clip, filter, build sort keys
// grid (67, BATCH), block 256
// ---------------------------------------------------------------------------
__global__ void proposal_prep(const float* __restrict__ iminfo)
{
    const int b = blockIdx.y;
    const int n = blockIdx.x * 256 + threadIdx.x;
    if (n >= NANCH) return;
    const int p = n / 9, a = n - 9 * p;

    float ax1, ay1, ax2, ay2;
    anchor_coords(n, ax1, ay1, ax2, ay2);

    const float* rb = g_reg + b * 36 * HW;
    float d0 = rb[(4 * a + 0) * HW + p];
    float d1 = rb[(4 * a + 1) * HW + p];
    float d2 = rb[(4 * a + 2) * HW + p];
    float d3 = rb[(4 * a + 3) * HW + p];

    float w  = ax2 - ax1 + 1.f, h = ay2 - ay1 + 1.f;
    float cx = ax1 + 0.5f * w,  cy = ay1 + 0.5f * h;
    float pcx = d0 * w + cx, pcy = d1 * h + cy;
    float pw = expf(d2) * w, ph = expf(d3) * h;

    float imh = iminfo[b * 3 + 0] - 1.f;
    float imw = iminfo[b * 3 + 1] - 1.f;
    float sc  = iminfo[b * 3 + 2];

    float x1 = fminf(fmaxf(pcx - 0.5f * pw, 0.f), imw);
    float y1 = fminf(fmaxf(pcy - 0.5f * ph, 0.f), imh);
    float x2 = fminf(fmaxf(pcx + 0.5f * pw, 0.f), imw);
    float y2 = fminf(fmaxf(pcy + 0.5f * ph, 0.f), imh);

    bool valid = (x2 - x1 + 1.f >= 16.f * sc) && (y2 - y1 + 1.f >= 16.f * sc);

    float s0 = g_cls[b * 18 * HW + a * HW + p];
    float s1 = g_cls[b * 18 * HW + (9 + a) * HW + p];
    float m  = fmaxf(s0, s1);
    float e0 = expf(s0 - m), e1 = expf(s1 - m);
    float sco = e1 / (e0 + e1);
    if (!valid) sco = -1e9f;

    g_keys[b * NANCH + n] =
        ((unsigned long long)(~f2u(sco)) << 32) | (unsigned)n;
    float4 bx = make_float4(x1, y1, x2, y2);
    ((float4*)g_boxes)[b * NANCH + n] = bx;
}

// ---------------------------------------------------------------------------
// radix-select rank 5999 + compact + bitonic sort 8192 in smem
// grid BATCH, block 1024, dyn smem 65536
// ---------------------------------------------------------------------------
__global__ void __launch_bounds__(1024) select_sort()
{
    unsigned long long* sb = (unsigned long long*)smem_raw;  // 8192 keys
    __shared__ unsigned int hist[256];
    __shared__ unsigned int pref[256];
    __shared__ unsigned long long s_cur;
    __shared__ int s_target;
    __shared__ int s_cnt;

    const int b = blockIdx.x;
    const int tid = threadIdx.x;
    const unsigned long long* kb = g_keys + b * NANCH;

    if (tid == 0) { s_cur = 0ull; s_target = PRE - 1; }
    __syncthreads();

    for (int pass = 0; pass < 8; pass++) {
        int shift = 56 - 8 * pass;
        if (tid < 256) hist[tid] = 0;
        __syncthreads();
        unsigned long long cur  = s_cur;
        unsigned long long mask = pass ? (~0ull << (64 - 8 * pass)) : 0ull;
        for (int i = tid; i < NANCH; i += 1024) {
            unsigned long long k = kb[i];
            if ((k & mask) == cur)
                atomicAdd(&hist[(unsigned)((k >> shift) & 255ull)], 1u);
        }
        __syncthreads();
        // parallel inclusive prefix over 256 buckets (Hillis-Steele)
        if (tid < 256) pref[tid] = hist[tid];
        __syncthreads();
        #pragma unroll
        for (int d = 1; d < 256; d <<= 1) {
            unsigned v = 0;
            if (tid < 256 && tid >= d) v = pref[tid - d];
            __syncthreads();
            if (tid < 256) pref[tid] += v;
            __syncthreads();
        }
        int tgt = s_target;
        __syncthreads();
        if (tid < 256) {
            unsigned incl = pref[tid];
            unsigned cnt  = hist[tid];
            unsigned excl = incl - cnt;
            if (cnt > 0 && (unsigned)tgt >= excl && (unsigned)tgt < incl) {
                s_cur = cur | ((unsigned long long)tid << shift);
                s_target = tgt - (int)excl;
            }
        }
        __syncthreads();
    }
    unsigned long long T = s_cur;

    for (int i = tid; i < 8192; i += 1024) sb[i] = ~0ull;
    if (tid == 0) s_cnt = 0;
    __syncthreads();
    for (int i = tid; i < NANCH; i += 1024) {
        unsigned long long k = kb[i];
        if (k <= T) { int pos = atomicAdd(&s_cnt, 1); sb[pos] = k; }
    }
    __syncthreads();

    for (int k2 = 2; k2 <= 8192; k2 <<= 1)
        for (int j = k2 >> 1; j > 0; j >>= 1) {
            for (int i = tid; i < 8192; i += 1024) {
                int ixj = i ^ j;
                if (ixj > i) {
                    unsigned long long a = sb[i], c = sb[ixj];
                    bool up = ((i & k2) == 0);
                    if ((a > c) == up) { sb[i] = c; sb[ixj] = a; }
                }
            }
            __syncthreads();
        }

    const float4* bb = (const float4*)(g_boxes) + b * NANCH;
    float4* tb = (float4*)(g_tops) + b * PRE;
    for (int r = tid; r < PRE; r += 1024) {
        int n = (int)(sb[r] & 0xFFFFFFFFull);
        tb[r] = bb[n];
    }
}

// ---------------------------------------------------------------------------
// NMS suppression bitmask. grid (NW, NW, BATCH), block 64
// ---------------------------------------------------------------------------
__global__ void nms_mask_k()
{
    const int b = blockIdx.z, rb = blockIdx.y, cb = blockIdx.x;
    const float4* tb = (const float4*)(g_tops) + b * PRE;
    __shared__ float4 cbox[64];
    const int t = threadIdx.x;
    const int j0 = cb * 64;
    const int jn = min(64, PRE - j0);
    if (t < jn) cbox[t] = tb[j0 + t];
    __syncthreads();
    const int i = rb * 64 + t;
    if (i >= PRE) return;
    float4 bi = tb[i];
    float areai = (bi.z - bi.x + 1.f) * (bi.w - bi.y + 1.f);
    unsigned long long m = 0ull;
    for (int jj = 0; jj < jn; jj++) {
        int j = j0 + jj;
        if (j <= i) continue;
        float4 bj = cbox[jj];
        float iw = fminf(bi.z, bj.z) - fmaxf(bi.x, bj.x) + 1.f;
        float ih = fminf(bi.w, bj.w) - fmaxf(bi.y, bj.y) + 1.f;
        if (iw > 0.f && ih > 0.f) {
            float inter = iw * ih;
            float aj = (bj.z - bj.x + 1.f) * (bj.w - bj.y + 1.f);
            float iou = inter / (areai + aj - inter);
            if (iou > NMS_TH) m |= (1ull << jj);
        }
    }
    g_mask[(b * PRE + i) * NW + cb] = m;
}

// ---------------------------------------------------------------------------
// serial keep scan (one warp per batch) with cp.async 8-row speculative
// prefetch ring + write rois
// ---------------------------------------------------------------------------
__global__ void nms_scan(float* __restrict__ out)
{
    const int b = blockIdx.x;
    const int lane = threadIdx.x;  // 32 threads
    __shared__ unsigned long long rem[NW];
    __shared__ int keep[POST];
    __shared__ __align__(16) unsigned long long ring[8][NW];
    for (int i = lane; i < NW; i += 32) rem[i] = 0ull;

    const unsigned ringaddr = (unsigned)__cvta_generic_to_shared(&ring[0][0]);
    const char* mbase = (const char*)g_mask + (size_t)b * PRE * NW * 8;

    // prefetch rows 0..7 (one commit group per row; groups complete in order)
    for (int r = 0; r < 8; r++) {
        for (int c = lane; c < 47; c += 32)
            cpa16(ringaddr + (unsigned)(r * NW * 8 + c * 16),
                  mbase + (size_t)r * NW * 8 + c * 16);
        CP_COMMIT();
    }
    __syncwarp();

    int cnt = 0;
    for (int i = 0; i < PRE && cnt < POST; i++) {
        CP_WAIT(7);          // 8 outstanding -> oldest (row i) complete
        __syncwarp();
        bool alive = !((rem[i >> 6] >> (i & 63)) & 1ull);
        if (alive) {
            const unsigned long long* mr = ring[i & 7];
            for (int c = lane; c < NW; c += 32) rem[c] |= mr[c];
            if (lane == 0) keep[cnt] = i;
            cnt++;
        }
        __syncwarp();
        int nr = i + 8;
        if (nr < PRE) {
            int slot = nr & 7;
            for (int c = lane; c < 47; c += 32)
                cpa16(ringaddr + (unsigned)(slot * NW * 8 + c * 16),
                      mbase + (size_t)nr * NW * 8 + c * 16);
        }
        CP_COMMIT();         // possibly empty group keeps wait arithmetic valid
    }
    CP_WAIT_ALL();
    __syncwarp();

    const float4* tb = (const float4*)(g_tops) + b * PRE;
    for (int k = lane; k < POST; k += 32) {
        int sel = (k < cnt) ? keep[k] : 0;   // jnp.nonzero fill_value=0
        float4 v = tb[sel];
        float* o = out + (size_t)(b * POST + k) * 5;
        o[0] = (float)b; o[1] = v.x; o[2] = v.y; o[3] = v.z; o[4] = v.w;
    }
}

// ---------------------------------------------------------------------------
// anchor target: IoU matrix + per-gt max. grid (67, BATCH), block 256
// ---------------------------------------------------------------------------
__global__ void at1(const float* __restrict__ gt, const float* __restrict__ iminfo)
{
    const int b = blockIdx.y;
    const int n = blockIdx.x * 256 + threadIdx.x;
    const int t = threadIdx.x;
    __shared__ float4 sgt[20];
    __shared__ unsigned int smax[20];
    if (t < 20) {
        const float* g = gt + (b * 20 + t) * 5;
        sgt[t] = make_float4(g[0], g[1], g[2], g[3]);
        smax[t] = 0u;
    }
    __syncthreads();

    if (n < NANCH) {
        float ax1, ay1, ax2, ay2;
        anchor_coords(n, ax1, ay1, ax2, ay2);
        bool inside = (ax1 >= 0.f) && (ay1 >= 0.f) &&
                      (ax2 < iminfo[b * 3 + 1]) && (ay2 < iminfo[b * 3 + 0]);
        float areaa = (ax2 - ax1 + 1.f) * (ay2 - ay1 + 1.f);
        float* ovrow = g_ov + (size_t)(b * NANCH + n) * 20;
        #pragma unroll
        for (int g = 0; g < 20; g++) {
            float4 G = sgt[g];
            float iw = fmaxf(fminf(ax2, G.z) - fmaxf(ax1, G.x) + 1.f, 0.f);
            float ih = fmaxf(fminf(ay2, G.w) - fmaxf(ay1, G.y) + 1.f, 0.f);
            float inter = iw * ih;
            float areab = (G.z - G.x + 1.f) * (G.w - G.y + 1.f);
            float o = inter / (areaa + areab - inter);
            if (!inside) o = -1.f;
            ovrow[g] = o;
            atomicMax(&smax[g], f2u(o));
        }
    }
    __syncthreads();
    if (t < 20) atomicMax(&g_gtmax[b * 20 + t], smax[t]);
}

// labels from overlaps. grid (67, BATCH), block 256
__global__ void at2()
{
    const int b = blockIdx.y;
    const int n = blockIdx.x * 256 + threadIdx.x;
    const int t = threadIdx.x;
    __shared__ float sgm[20];
    if (t < 20) sgm[t] = u2f(g_gtmax[b * 20 + t]);
    __syncthreads();
    if (n >= NANCH) return;

    const float* ovrow = g_ov + (size_t)(b * NANCH + n) * 20;
    float mo = -2.f; int am = 0; bool isg = false;
    #pragma unroll
    for (int g = 0; g < 20; g++) {
        float v = ovrow[g];
        if (v > mo) { mo = v; am = g; }
        if (v == sgm[g] && sgm[g] > 0.f) isg = true;
    }
    bool inside = (mo >= 0.f);   // inside anchors always have IoU >= 0
    int lab = -1;
    if (inside && mo < 0.3f) lab = 0;
    if (inside && isg)       lab = 1;
    if (inside && mo >= 0.7f) lab = 1;
    g_labels[b * NANCH + n] = lab;
    g_amax  [b * NANCH + n] = am;
}

// sequential cumsum caps (single block per batch, 1024 threads)
__device__ int capped_pass(int* L, int flagval, int cap)
{
    __shared__ int wsum[32];
    __shared__ int run;
    const int tid = threadIdx.x;
    const int wid = tid >> 5;
    if (tid == 0) run = 0;
    __syncthreads();
    for (int base = 0; base < NANCH; base += 1024) {
        int i = base + tid;
        int f = 0;
        if (i < NANCH) f = (L[i] == flagval) ? 1 : 0;
        int v = f;
        #pragma unroll
        for (int d = 1; d < 32; d <<= 1) {
            int x = __shfl_up_sync(0xFFFFFFFFu, v, d);
            if ((tid & 31) >= d) v += x;
        }
        if ((tid & 31) == 31) wsum[wid] = v;
        __syncthreads();
        if (wid == 0) {
            int w = wsum[tid & 31];
            #pragma unroll
            for (int d = 1; d < 32; d <<= 1) {
                int x = __shfl_up_sync(0xFFFFFFFFu, w, d);
                if ((tid & 31) >= d) w += x;
            }
            wsum[tid & 31] = w;
        }
        __syncthreads();
        int offset = (wid > 0) ? wsum[wid - 1] : 0;
        int incl = run + offset + v;
        if (i < NANCH && f && incl > cap) L[i] = -1;
        __syncthreads();
        if (tid == 0) run += wsum[31];
        __syncthreads();
    }
    return run;   // total flags (pre-cap); same value for all threads
}

__global__ void __launch_bounds__(1024) at3()
{
    const int b = blockIdx.x;
    int* L = g_labels + b * NANCH;
    int totfg = capped_pass(L, 1, 128);
    int fg_kept = min(totfg, 128);
    int num_bg = 256 - fg_kept;
    int totbg = capped_pass(L, 0, num_bg);
    int bg_kept = min(totbg, num_bg);
    if (threadIdx.x == 0) g_nex[b] = fg_kept + bg_kept;
}

// ---------------------------------------------------------------------------
// loss reduction. grid (67, BATCH), block 256
// ---------------------------------------------------------------------------
__global__ void loss_kernel(const float* __restrict__ gt)
{
    const int b = blockIdx.y;
    const int n = blockIdx.x * 256 + threadIdx.x;
    float np = 0.f, cn = 0.f, rs = 0.f;
    if (n < NANCH) {
        int lab = g_labels[b * NANCH + n];
        if (lab != -1) {
            int p = n / 9, a = n - 9 * p;
            float s0 = g_cls[b * 18 * HW + a * HW + p];
            float s1 = g_cls[b * 18 * HW + (9 + a) * HW + p];
            float m = fmaxf(s0, s1);
            float lse = m + logf(expf(s0 - m) + expf(s1 - m));
            float pick = ((lab == 1) ? s1 : s0) - lse;
            np = -pick; cn = 1.f;
            if (lab == 1) {
                float ax1, ay1, ax2, ay2;
                anchor_coords(n, ax1, ay1, ax2, ay2);
                int g = g_amax[b * NANCH + n];
                const float* G = gt + (b * 20 + g) * 5;
                float ew = ax2 - ax1 + 1.f, eh = ay2 - ay1 + 1.f;
                float ecx = ax1 + 0.5f * ew, ecy = ay1 + 0.5f * eh;
                float gw = G[2] - G[0] + 1.f, gh = G[3] - G[1] + 1.f;
                float gcx = G[0] + 0.5f * gw, gcy = G[1] + 0.5f * gh;
                float t0 = (gcx - ecx) / ew;
                float t1 = (gcy - ecy) / eh;
                float t2 = logf(gw / ew);
                float t3 = logf(gh / eh);
                const float* rb = g_reg + b * 36 * HW;
                float d0 = rb[(4 * a + 0) * HW + p] - t0;
                float d1 = rb[(4 * a + 1) * HW + p] - t1;
                float d2 = rb[(4 * a + 2) * HW + p] - t2;
                float d3 = rb[(4 * a + 3) * HW + p] - t3;
                rs = smooth1(d0) + smooth1(d1) + smooth1(d2) + smooth1(d3);
            }
        }
    }
    __shared__ float r0[256], r1[256], r2[256];
    const int tid = threadIdx.x;
    r0[tid] = np; r1[tid] = cn; r2[tid] = rs;
    __syncthreads();
    for (int s = 128; s > 0; s >>= 1) {
        if (tid < s) { r0[tid] += r0[tid + s]; r1[tid] += r1[tid + s]; r2[tid] += r2[tid + s]; }
        __syncthreads();
    }
    if (tid == 0) {
        atomicAdd(&g_acc[0], r0[0]);
        atomicAdd(&g_acc[1], r1[0]);
        atomicAdd(&g_acc[2 + b], r2[0]);
    }
}

__global__ void finalize(float* __restrict__ out)
{
    float cnt = fmaxf(g_acc[1], 1.f);
    out[BATCH * POST * 5 + 0] = g_acc[0] / cnt;
    float rr0 = g_acc[2] / fmaxf((float)g_nex[0], 1.f);
    float rr1 = g_acc[3] / fmaxf((float)g_nex[1], 1.f);
    out[BATCH * POST * 5 + 1] = 0.5f * (rr0 + rr1);
}

// ---------------------------------------------------------------------------
// launcher
// ---------------------------------------------------------------------------
extern "C" void kernel_launch(void* const* d_in, const int* in_sizes, int n_in,
                              void* d_out, int out_size)
{
    const float* feature = (const float*)d_in[0];
    const float* gt      = (const float*)d_in[1];
    const float* iminfo  = (const float*)d_in[2];
    const float* wconv   = (const float*)d_in[3];
    const float* bconv   = (const float*)d_in[4];
    const float* wcls    = (const float*)d_in[5];
    const float* bcls    = (const float*)d_in[6];
    const float* wreg    = (const float*)d_in[7];
    const float* breg    = (const float*)d_in[8];
    float* out = (float*)d_out;

    cudaFuncSetAttribute(conv3_gemm, cudaFuncAttributeMaxDynamicSharedMemorySize, C3_SMEM_BYTES);
    cudaFuncSetAttribute(conv1x1, cudaFuncAttributeMaxDynamicSharedMemorySize, C1_SMEM_BYTES);
    cudaFuncSetAttribute(select_sort, cudaFuncAttributeMaxDynamicSharedMemorySize, 65536);

    init_zero<<<1, 64>>>();
    conv3_gemm<<<dim3(15, 8, BATCH), 256, C3_SMEM_BYTES>>>(feature, wconv, bconv);
    conv1x1<<<dim3(60, BATCH), 256, C1_SMEM_BYTES>>>(wcls, bcls, wreg, breg);
    proposal_prep<<<dim3(67, BATCH), 256>>>(iminfo);
    select_sort<<<BATCH, 1024, 65536>>>();
    nms_mask_k<<<dim3(NW, NW, BATCH), 64>>>();
    nms_scan<<<BATCH, 32>>>(out);
    at1<<<dim3(67, BATCH), 256>>>(gt, iminfo);
    at2<<<dim3(67, BATCH), 256>>>();
    at3<<<BATCH, 1024>>>();
    loss_kernel<<<dim3(67, BATCH), 256>>>(gt);
    finalize<<<1, 1>>>(out);
}

// round 12
// speedup vs baseline: 1.1585x; 1.1585x over previous
#include <cuda_runtime.h>
#include <cuda_bf16.h>

// ---------------------------------------------------------------------------
// Problem constants
// ---------------------------------------------------------------------------
#define BATCH   2
#define HF      38
#define WF      50
#define HW      1900          // HF*WF
#define ANUM    9
#define NANCH   17100         // HW*ANUM
#define CIN     1024
#define CMID    512
#define K9      9216          // CIN*9
#define KT      64
#define NKT     (K9 / KT)     // 144
#define AP      132           // padded A width (4-way instead of 32-way STS conflict)
#define PRE     6000
#define POST    300
#define NW      94            // ceil(PRE/64)
#define NMS_TH  0.7f

// canonical Faster-RCNN base anchors (base=16, ratios .5/1/2, scales 8/16/32)
__constant__ float c_base[9][4] = {
    {-84.f,  -40.f,  99.f,  55.f},
    {-176.f, -88.f, 191.f, 103.f},
    {-360.f,-184.f, 375.f, 199.f},
    {-56.f,  -56.f,  71.f,  71.f},
    {-120.f,-120.f, 135.f, 135.f},
    {-248.f,-248.f, 263.f, 263.f},
    {-36.f,  -80.f,  51.f,  95.f},
    {-80.f, -168.f,  95.f, 183.f},
    {-168.f,-344.f, 183.f, 359.f}
};

// ---------------------------------------------------------------------------
// Scratch (static device allocations; runtime alloc is forbidden)
// ---------------------------------------------------------------------------
__device__ float               g_x    [BATCH * CMID * HW];   // conv3+relu out
__device__ float               g_cls  [BATCH * 18 * HW];
__device__ float               g_reg  [BATCH * 36 * HW];
__device__ unsigned long long  g_keys [BATCH * NANCH];
__device__ float               g_boxes[BATCH * NANCH * 4];
__device__ float               g_tops [BATCH * PRE * 4];
__device__ unsigned long long  g_mask [BATCH * PRE * NW];
__device__ int                 g_labels[BATCH * NANCH];
__device__ int                 g_amax [BATCH * NANCH];
__device__ unsigned int        g_gtmax[BATCH * 20];
__device__ float               g_acc  [4];                   // negpick, cnt, reg0, reg1
__device__ int                 g_nex  [BATCH];

// ---------------------------------------------------------------------------
// helpers
// ---------------------------------------------------------------------------
__device__ __forceinline__ unsigned f2u(float f) {
    unsigned u = __float_as_uint(f);
    return (u & 0x80000000u) ? ~u : (u | 0x80000000u);
}
__device__ __forceinline__ float u2f(unsigned u) {
    unsigned bits = (u & 0x80000000u) ? (u & 0x7FFFFFFFu) : ~u;
    return __uint_as_float(bits);
}
__device__ __forceinline__ void anchor_coords(int n, float& ax1, float& ay1,
                                              float& ax2, float& ay2) {
    int p = n / 9, a = n - 9 * p;
    int y = p / WF, x = p - WF * y;
    float sx = 16.f * x, sy = 16.f * y;
    ax1 = c_base[a][0] + sx; ay1 = c_base[a][1] + sy;
    ax2 = c_base[a][2] + sx; ay2 = c_base[a][3] + sy;
}
__device__ __forceinline__ float smooth1(float d) {
    float ad = fabsf(d);
    return (ad < (1.0f / 9.0f)) ? (4.5f * d * d) : (ad - 0.5f / 9.0f);
}

// packed f32x2 ops (bit-identical to two independent scalar IEEE ops)
typedef unsigned long long ull;
#define SGN2 0x8000000080000000ULL
__device__ __forceinline__ ull dup2(float s) {
    ull d; asm("mov.b64 %0, {%1, %1};" : "=l"(d) : "f"(s)); return d;
}
__device__ __forceinline__ ull fma2(ull a, ull b, ull c) {
    ull d; asm("fma.rn.f32x2 %0, %1, %2, %3;" : "=l"(d) : "l"(a), "l"(b), "l"(c));
    return d;
}
__device__ __forceinline__ ull add2(ull a, ull b) {
    ull d; asm("add.rn.f32x2 %0, %1, %2;" : "=l"(d) : "l"(a), "l"(b)); return d;
}
__device__ __forceinline__ ull sub2(ull a, ull b) {   // a + (-b), same rounding as scalar sub
    return add2(a, b ^ SGN2);
}
__device__ __forceinline__ void unpack2(ull v, float& lo, float& hi) {
    asm("mov.b64 {%0, %1}, %2;" : "=f"(lo), "=f"(hi) : "l"(v));
}

// cp.async helpers
__device__ __forceinline__ void cpa4(unsigned dst, const void* src, int srcsz) {
    asm volatile("cp.async.ca.shared.global [%0], [%1], 4, %2;"
                 :: "r"(dst), "l"(src), "r"(srcsz));
}
__device__ __forceinline__ void cpa16(unsigned dst, const void* src) {
    asm volatile("cp.async.cg.shared.global [%0], [%1], 16;"
                 :: "r"(dst), "l"(src));
}
#define CP_COMMIT()   asm volatile("cp.async.commit_group;")
#define CP_WAIT(n)    asm volatile("cp.async.wait_group %0;" :: "n"(n))
#define CP_WAIT_ALL() asm volatile("cp.async.wait_all;")

// ---------------------------------------------------------------------------
// zero-init kernel (accumulators)
// ---------------------------------------------------------------------------
__global__ void init_zero() {
    int t = threadIdx.x;
    if (t < 4)  g_acc[t] = 0.f;
    if (t < BATCH * 20) g_gtmax[t] = 0u;
}

// ---------------------------------------------------------------------------
// conv3x3 1024->512 as implicit-GEMM, 128x128 tiles, KT=64, f32x2 packed FMA,
// Kahan-compensated per-tile merge, cp.async DOUBLE-BUFFERED pipeline.
// grid (15, 4, BATCH), block 512, micro-tile 8(m, 4 pairs) x 4(n).
// dyn smem: 2 x A[KT][AP] + 2 x B[KT][128] = 133120 B.  (exact R8 config)
// ---------------------------------------------------------------------------
extern __shared__ unsigned char smem_raw[];

#define C3_A_FLOATS (KT * AP)     // 8448
#define C3_B_FLOATS (KT * 128)    // 8192
#define C3_SMEM_BYTES ((2 * C3_A_FLOATS + 2 * C3_B_FLOATS) * 4)  // 133120

__global__ void __launch_bounds__(512) conv3_gemm(
    const float* __restrict__ feat, const float* __restrict__ wconv,
    const float* __restrict__ bconv)
{
    float* AsBuf = (float*)smem_raw;                 // [2][KT][AP]
    float* BsBuf = AsBuf + 2 * C3_A_FLOATS;          // [2][KT][128]
    const unsigned sA = (unsigned)__cvta_generic_to_shared(AsBuf);
    const unsigned sB = (unsigned)__cvta_generic_to_shared(BsBuf);

    const int b  = blockIdx.z;
    const int m0 = blockIdx.y * 128;
    const int n0 = blockIdx.x * 128;
    const int tid = threadIdx.x;

    ull acc2[16], comp2[16];
    #pragma unroll
    for (int e = 0; e < 16; e++) { acc2[e] = 0ULL; comp2[e] = 0ULL; }

    const int bcol = tid & 127;
    const int p    = n0 + bcol;
    const int py   = p / WF, px = p - WF * (p / WF);
    const bool pvalid = p < HW;
    const float* fb = feat + b * (CIN * HW);

    const int tm = (tid >> 5) << 3;   // warp-uniform: 0..120
    const int tn = (tid & 31) << 2;   // 0..124
    const int krow0 = tid >> 7;       // 0..3

    auto issue_tile = [&](int kt, int buf) {
        // A tile: 128 m x 64 k = 8192 elems, 16 x cp.async 4B per thread
        #pragma unroll
        for (int r = 0; r < 16; r++) {
            int e = tid + 512 * r;
            int row = e >> 6, col = e & 63;
            const float* src = &wconv[(m0 + row) * K9 + kt * KT + col];
            unsigned dst = sA + (unsigned)((buf * KT + col) * AP + row) * 4u;
            cpa4(dst, src, 4);
        }
        // B tile (im2col): 64 k-rows x 128 cols, 16 x cp.async 4B,
        // zero-fill when out of bounds
        #pragma unroll
        for (int r = 0; r < 16; r++) {
            int krow = krow0 + 4 * r;
            int kg = kt * KT + krow;
            int c = kg / 9;
            int t = kg - 9 * c;
            int dy = t / 3 - 1;
            int dx = t - (t / 3) * 3 - 1;
            int yy = py + dy, xx = px + dx;
            bool valid = pvalid && (unsigned)yy < (unsigned)HF && (unsigned)xx < (unsigned)WF;
            const float* src = valid ? &fb[c * HW + yy * WF + xx] : fb;
            unsigned dst = sB + (unsigned)((buf * KT + krow) * 128 + bcol) * 4u;
            cpa4(dst, src, valid ? 4 : 0);
        }
        CP_COMMIT();
    };

    issue_tile(0, 0);
    CP_WAIT(0);
    __syncthreads();

    for (int kt = 0; kt < NKT; kt++) {
        const int cur = kt & 1;
        if (kt + 1 < NKT) issue_tile(kt + 1, cur ^ 1);

        const float* As_cur = AsBuf + cur * C3_A_FLOATS;
        const float* Bs_cur = BsBuf + cur * C3_B_FLOATS;

        ull part2[16];
        #pragma unroll
        for (int e = 0; e < 16; e++) part2[e] = 0ULL;

        #pragma unroll 8
        for (int kk = 0; kk < KT; kk++) {
            const ulonglong2* ap = (const ulonglong2*)&As_cur[kk * AP + tm];
            ulonglong2 a01 = ap[0];
            ulonglong2 a23 = ap[1];
            ull am[4] = {a01.x, a01.y, a23.x, a23.y};
            float4 bq = *(const float4*)&Bs_cur[kk * 128 + tn];
            ull bd[4] = {dup2(bq.x), dup2(bq.y), dup2(bq.z), dup2(bq.w)};
            #pragma unroll
            for (int mp = 0; mp < 4; mp++)
                #pragma unroll
                for (int j = 0; j < 4; j++)
                    part2[mp * 4 + j] = fma2(am[mp], bd[j], part2[mp * 4 + j]);
        }
        // Kahan merge of the 64-product partial into the running sum (f32x2)
        #pragma unroll
        for (int e = 0; e < 16; e++) {
            ull y = sub2(part2[e], comp2[e]);
            ull t = add2(acc2[e], y);
            comp2[e] = sub2(sub2(t, acc2[e]), y);
            acc2[e] = t;
        }
        if (kt + 1 < NKT) CP_WAIT(0);
        __syncthreads();
    }
    #pragma unroll
    for (int mp = 0; mp < 4; mp++) {
        int co0 = m0 + tm + 2 * mp;
        float b0 = bconv[co0], b1 = bconv[co0 + 1];
        #pragma unroll
        for (int j = 0; j < 4; j++) {
            int pp = n0 + tn + j;
            if (pp < HW) {
                float lo, hi;
                unpack2(acc2[mp * 4 + j], lo, hi);
                float v0 = lo + b0, v1 = hi + b1;
                g_x[b * (CMID * HW) + co0 * HW + pp]       = v0 > 0.f ? v0 : 0.f;
                g_x[b * (CMID * HW) + (co0 + 1) * HW + pp] = v1 > 0.f ? v1 : 0.f;
            }
        }
    }
}

// ---------------------------------------------------------------------------
// fused 1x1 convs (cls 18 + reg 36), Kahan accumulation, 8-way K-split.
// grid (60, BATCH), block 256 = 32 positions x 8 K-chunks of 64 channels.
// ALL in dynamic smem: wT [512][54] (110592 B) + partials [32][54][8]
// (55296 B) = 165888 B. Deterministic fixed-order merge (no float atomics).
// ---------------------------------------------------------------------------
#define C1_POS 32
#define C1_KS  8
#define C1_WT_FLOATS (512 * 54)
#define C1_SMEM_BYTES ((C1_WT_FLOATS + C1_POS * 54 * C1_KS) * 4)

__global__ void __launch_bounds__(256) conv1x1(
    const float* __restrict__ wcls, const float* __restrict__ bcls,
    const float* __restrict__ wreg, const float* __restrict__ breg)
{
    float* wT = (float*)smem_raw;                 // [512][54]
    float* sp = wT + C1_WT_FLOATS;                // [32][54][8]
    const int b  = blockIdx.y;
    const int p0 = blockIdx.x * C1_POS;
    const int tid = threadIdx.x;
    const int pos = tid & 31;
    const int ks  = tid >> 5;      // 0..7

    for (int e = tid; e < 512 * 18; e += 256) {
        int o = e / 512, c = e - 512 * o;
        wT[c * 54 + o] = wcls[e];
    }
    for (int e = tid; e < 512 * 36; e += 256) {
        int o = e / 512, c = e - 512 * o;
        wT[c * 54 + 18 + o] = wreg[e];
    }
    __syncthreads();

    const int p = p0 + pos;
    const bool v = p < HW;
    float acc[54], comp[54];
    #pragma unroll
    for (int o = 0; o < 54; o++) { acc[o] = 0.f; comp[o] = 0.f; }

    const float* xb = g_x + b * (CMID * HW) + (v ? p : 0);
    const int c0 = ks * 64;
    for (int c = c0; c < c0 + 64; c++) {
        float xv = v ? xb[c * HW] : 0.f;
        const float* w = &wT[c * 54];
        #pragma unroll
        for (int o = 0; o < 54; o++) {
            float y = __fmaf_rn(xv, w[o], -comp[o]);
            float t = __fadd_rn(acc[o], y);
            comp[o] = __fsub_rn(__fsub_rn(t, acc[o]), y);
            acc[o] = t;
        }
    }
    #pragma unroll
    for (int o = 0; o < 54; o++) sp[(pos * 54 + o) * C1_KS + ks] = acc[o];
    __syncthreads();

    // merge 8 partials per (pos, o) in fixed order -> deterministic
    for (int e = tid; e < C1_POS * 54; e += 256) {
        int pos2 = e / 54, o = e - 54 * pos2;
        int pp = p0 + pos2;
        if (pp >= HW) continue;
        float s = 0.f;
        #pragma unroll
        for (int k = 0; k < C1_KS; k++) s = __fadd_rn(s, sp[(pos2 * 54 + o) * C1_KS + k]);
        if (o < 18) g_cls[b * 18 * HW + o * HW + pp] = s + bcls[o];
        else        g_reg[b * 36 * HW + (o - 18) * HW + pp] = s + breg[o - 18];
    }
}

// ---------------------------------------------------------------------------
// proposal prep: decode boxes, clip, filter, build sort keys
// grid (67, BATCH), block 256
// ---------------------------------------------------------------------------
__global__ void proposal_prep(const float* __restrict__ iminfo)
{
    const int b = blockIdx.y;
    const int n = blockIdx.x * 256 + threadIdx.x;
    if (n >= NANCH) return;
    const int p = n / 9, a = n - 9 * p;

    float ax1, ay1, ax2, ay2;
    anchor_coords(n, ax1, ay1, ax2, ay2);

    const float* rb = g_reg + b * 36 * HW;
    float d0 = rb[(4 * a + 0) * HW + p];
    float d1 = rb[(4 * a + 1) * HW + p];
    float d2 = rb[(4 * a + 2) * HW + p];
    float d3 = rb[(4 * a + 3) * HW + p];

    float w  = ax2 - ax1 + 1.f, h = ay2 - ay1 + 1.f;
    float cx = ax1 + 0.5f * w,  cy = ay1 + 0.5f * h;
    float pcx = d0 * w + cx, pcy = d1 * h + cy;
    float pw = expf(d2) * w, ph = expf(d3) * h;

    float imh = iminfo[b * 3 + 0] - 1.f;
    float imw = iminfo[b * 3 + 1] - 1.f;
    float sc  = iminfo[b * 3 + 2];

    float x1 = fminf(fmaxf(pcx - 0.5f * pw, 0.f), imw);
    float y1 = fminf(fmaxf(pcy - 0.5f * ph, 0.f), imh);
    float x2 = fminf(fmaxf(pcx + 0.5f * pw, 0.f), imw);
    float y2 = fminf(fmaxf(pcy + 0.5f * ph, 0.f), imh);

    bool valid = (x2 - x1 + 1.f >= 16.f * sc) && (y2 - y1 + 1.f >= 16.f * sc);

    float s0 = g_cls[b * 18 * HW + a * HW + p];
    float s1 = g_cls[b * 18 * HW + (9 + a) * HW + p];
    float m  = fmaxf(s0, s1);
    float e0 = expf(s0 - m), e1 = expf(s1 - m);
    float sco = e1 / (e0 + e1);
    if (!valid) sco = -1e9f;

    g_keys[b * NANCH + n] =
        ((unsigned long long)(~f2u(sco)) << 32) | (unsigned)n;
    float4 bx = make_float4(x1, y1, x2, y2);
    ((float4*)g_boxes)[b * NANCH + n] = bx;
}

// ---------------------------------------------------------------------------
// radix-select rank 5999 + compact + bitonic sort 8192 in smem
// grid BATCH, block 1024, dyn smem 65536
// ---------------------------------------------------------------------------
__global__ void __launch_bounds__(1024) select_sort()
{
    unsigned long long* sb = (unsigned long long*)smem_raw;  // 8192 keys
    __shared__ unsigned int hist[256];
    __shared__ unsigned int pref[256];
    __shared__ unsigned long long s_cur;
    __shared__ int s_target;
    __shared__ int s_cnt;

    const int b = blockIdx.x;
    const int tid = threadIdx.x;
    const unsigned long long* kb = g_keys + b * NANCH;

    if (tid == 0) { s_cur = 0ull; s_target = PRE - 1; }
    __syncthreads();

    for (int pass = 0; pass < 8; pass++) {
        int shift = 56 - 8 * pass;
        if (tid < 256) hist[tid] = 0;
        __syncthreads();
        unsigned long long cur  = s_cur;
        unsigned long long mask = pass ? (~0ull << (64 - 8 * pass)) : 0ull;
        for (int i = tid; i < NANCH; i += 1024) {
            unsigned long long k = kb[i];
            if ((k & mask) == cur)
                atomicAdd(&hist[(unsigned)((k >> shift) & 255ull)], 1u);
        }
        __syncthreads();
        // parallel inclusive prefix over 256 buckets (Hillis-Steele)
        if (tid < 256) pref[tid] = hist[tid];
        __syncthreads();
        #pragma unroll
        for (int d = 1; d < 256; d <<= 1) {
            unsigned v = 0;
            if (tid < 256 && tid >= d) v = pref[tid - d];
            __syncthreads();
            if (tid < 256) pref[tid] += v;
            __syncthreads();
        }
        int tgt = s_target;
        __syncthreads();
        if (tid < 256) {
            unsigned incl = pref[tid];
            unsigned cnt  = hist[tid];
            unsigned excl = incl - cnt;
            if (cnt > 0 && (unsigned)tgt >= excl && (unsigned)tgt < incl) {
                s_cur = cur | ((unsigned long long)tid << shift);
                s_target = tgt - (int)excl;
            }
        }
        __syncthreads();
    }
    unsigned long long T = s_cur;

    for (int i = tid; i < 8192; i += 1024) sb[i] = ~0ull;
    if (tid == 0) s_cnt = 0;
    __syncthreads();
    for (int i = tid; i < NANCH; i += 1024) {
        unsigned long long k = kb[i];
        if (k <= T) { int pos = atomicAdd(&s_cnt, 1); sb[pos] = k; }
    }
    __syncthreads();

    for (int k2 = 2; k2 <= 8192; k2 <<= 1)
        for (int j = k2 >> 1; j > 0; j >>= 1) {
            for (int i = tid; i < 8192; i += 1024) {
                int ixj = i ^ j;
                if (ixj > i) {
                    unsigned long long a = sb[i], c = sb[ixj];
                    bool up = ((i & k2) == 0);
                    if ((a > c) == up) { sb[i] = c; sb[ixj] = a; }
                }
            }
            __syncthreads();
        }

    const float4* bb = (const float4*)(g_boxes) + b * NANCH;
    float4* tb = (float4*)(g_tops) + b * PRE;
    for (int r = tid; r < PRE; r += 1024) {
        int n = (int)(sb[r] & 0xFFFFFFFFull);
        tb[r] = bb[n];
    }
}

// ---------------------------------------------------------------------------
// NMS suppression bitmask. grid (NW, NW, BATCH), block 64
// ---------------------------------------------------------------------------
__global__ void nms_mask_k()
{
    const int b = blockIdx.z, rb = blockIdx.y, cb = blockIdx.x;
    const float4* tb = (const float4*)(g_tops) + b * PRE;
    __shared__ float4 cbox[64];
    const int t = threadIdx.x;
    const int j0 = cb * 64;
    const int jn = min(64, PRE - j0);
    if (t < jn) cbox[t] = tb[j0 + t];
    __syncthreads();
    const int i = rb * 64 + t;
    if (i >= PRE) return;
    float4 bi = tb[i];
    float areai = (bi.z - bi.x + 1.f) * (bi.w - bi.y + 1.f);
    unsigned long long m = 0ull;
    for (int jj = 0; jj < jn; jj++) {
        int j = j0 + jj;
        if (j <= i) continue;
        float4 bj = cbox[jj];
        float iw = fminf(bi.z, bj.z) - fmaxf(bi.x, bj.x) + 1.f;
        float ih = fminf(bi.w, bj.w) - fmaxf(bi.y, bj.y) + 1.f;
        if (iw > 0.f && ih > 0.f) {
            float inter = iw * ih;
            float aj = (bj.z - bj.x + 1.f) * (bj.w - bj.y + 1.f);
            float iou = inter / (areai + aj - inter);
            if (iou > NMS_TH) m |= (1ull << jj);
        }
    }
    g_mask[(b * PRE + i) * NW + cb] = m;
}

// ---------------------------------------------------------------------------
// serial keep scan (one warp per batch) with cp.async 8-row speculative
// prefetch ring + write rois
// ---------------------------------------------------------------------------
__global__ void nms_scan(float* __restrict__ out)
{
    const int b = blockIdx.x;
    const int lane = threadIdx.x;  // 32 threads
    __shared__ unsigned long long rem[NW];
    __shared__ int keep[POST];
    __shared__ __align__(16) unsigned long long ring[8][NW];
    for (int i = lane; i < NW; i += 32) rem[i] = 0ull;

    const unsigned ringaddr = (unsigned)__cvta_generic_to_shared(&ring[0][0]);
    const char* mbase = (const char*)g_mask + (size_t)b * PRE * NW * 8;

    // prefetch rows 0..7 (one commit group per row; groups complete in order)
    for (int r = 0; r < 8; r++) {
        for (int c = lane; c < 47; c += 32)
            cpa16(ringaddr + (unsigned)(r * NW * 8 + c * 16),
                  mbase + (size_t)r * NW * 8 + c * 16);
        CP_COMMIT();
    }
    __syncwarp();

    int cnt = 0;
    for (int i = 0; i < PRE && cnt < POST; i++) {
        CP_WAIT(7);          // 8 outstanding -> oldest (row i) complete
        __syncwarp();
        bool alive = !((rem[i >> 6] >> (i & 63)) & 1ull);
        if (alive) {
            const unsigned long long* mr = ring[i & 7];
            for (int c = lane; c < NW; c += 32) rem[c] |= mr[c];
            if (lane == 0) keep[cnt] = i;
            cnt++;
        }
        __syncwarp();
        int nr = i + 8;
        if (nr < PRE) {
            int slot = nr & 7;
            for (int c = lane; c < 47; c += 32)
                cpa16(ringaddr + (unsigned)(slot * NW * 8 + c * 16),
                      mbase + (size_t)nr * NW * 8 + c * 16);
        }
        CP_COMMIT();         // possibly empty group keeps wait arithmetic valid
    }
    CP_WAIT_ALL();
    __syncwarp();

    const float4* tb = (const float4*)(g_tops) + b * PRE;
    for (int k = lane; k < POST; k += 32) {
        int sel = (k < cnt) ? keep[k] : 0;   // jnp.nonzero fill_value=0
        float4 v = tb[sel];
        float* o = out + (size_t)(b * POST + k) * 5;
        o[0] = (float)b; o[1] = v.x; o[2] = v.y; o[3] = v.z; o[4] = v.w;
    }
}

// ---------------------------------------------------------------------------
// anchor target pass 1: per-gt max IoU only (no g_ov materialization).
// grid (67, BATCH), block 256
// ---------------------------------------------------------------------------
__global__ void at1(const float* __restrict__ gt, const float* __restrict__ iminfo)
{
    const int b = blockIdx.y;
    const int n = blockIdx.x * 256 + threadIdx.x;
    const int t = threadIdx.x;
    __shared__ float4 sgt[20];
    __shared__ unsigned int smax[20];
    if (t < 20) {
        const float* g = gt + (b * 20 + t) * 5;
        sgt[t] = make_float4(g[0], g[1], g[2], g[3]);
        smax[t] = 0u;
    }
    __syncthreads();

    if (n < NANCH) {
        float ax1, ay1, ax2, ay2;
        anchor_coords(n, ax1, ay1, ax2, ay2);
        bool inside = (ax1 >= 0.f) && (ay1 >= 0.f) &&
                      (ax2 < iminfo[b * 3 + 1]) && (ay2 < iminfo[b * 3 + 0]);
        float areaa = (ax2 - ax1 + 1.f) * (ay2 - ay1 + 1.f);
        #pragma unroll
        for (int g = 0; g < 20; g++) {
            float4 G = sgt[g];
            float iw = fmaxf(fminf(ax2, G.z) - fmaxf(ax1, G.x) + 1.f, 0.f);
            float ih = fmaxf(fminf(ay2, G.w) - fmaxf(ay1, G.y) + 1.f, 0.f);
            float inter = iw * ih;
            float areab = (G.z - G.x + 1.f) * (G.w - G.y + 1.f);
            float o = inter / (areaa + areab - inter);
            if (!inside) o = -1.f;
            atomicMax(&smax[g], f2u(o));
        }
    }
    __syncthreads();
    if (t < 20) atomicMax(&g_gtmax[b * 20 + t], smax[t]);
}

// anchor target pass 2: labels from RECOMPUTED IoUs (identical formula on
// identical inputs -> identical values to pass 1). grid (67, BATCH), block 256
__global__ void at2(const float* __restrict__ gt, const float* __restrict__ iminfo)
{
    const int b = blockIdx.y;
    const int n = blockIdx.x * 256 + threadIdx.x;
    const int t = threadIdx.x;
    __shared__ float4 sgt[20];
    __shared__ float sgm[20];
    if (t < 20) {
        const float* g = gt + (b * 20 + t) * 5;
        sgt[t] = make_float4(g[0], g[1], g[2], g[3]);
        sgm[t] = u2f(g_gtmax[b * 20 + t]);
    }
    __syncthreads();
    if (n >= NANCH) return;

    float ax1, ay1, ax2, ay2;
    anchor_coords(n, ax1, ay1, ax2, ay2);
    bool inside = (ax1 >= 0.f) && (ay1 >= 0.f) &&
                  (ax2 < iminfo[b * 3 + 1]) && (ay2 < iminfo[b * 3 + 0]);
    float areaa = (ax2 - ax1 + 1.f) * (ay2 - ay1 + 1.f);

    float mo = -2.f; int am = 0; bool isg = false;
    #pragma unroll
    for (int g = 0; g < 20; g++) {
        float4 G = sgt[g];
        float iw = fmaxf(fminf(ax2, G.z) - fmaxf(ax1, G.x) + 1.f, 0.f);
        float ih = fmaxf(fminf(ay2, G.w) - fmaxf(ay1, G.y) + 1.f, 0.f);
        float inter = iw * ih;
        float areab = (G.z - G.x + 1.f) * (G.w - G.y + 1.f);
        float v = inter / (areaa + areab - inter);
        if (!inside) v = -1.f;
        if (v > mo) { mo = v; am = g; }
        if (v == sgm[g] && sgm[g] > 0.f) isg = true;
    }
    int lab = -1;
    if (inside && mo < 0.3f) lab = 0;
    if (inside && isg)       lab = 1;
    if (inside && mo >= 0.7f) lab = 1;
    g_labels[b * NANCH + n] = lab;
    g_amax  [b * NANCH + n] = am;
}

// sequential cumsum caps (single block per batch, 1024 threads)
__device__ int capped_pass(int* L, int flagval, int cap)
{
    __shared__ int wsum[32];
    __shared__ int run;
    const int tid = threadIdx.x;
    const int wid = tid >> 5;
    if (tid == 0) run = 0;
    __syncthreads();
    for (int base = 0; base < NANCH; base += 1024) {
        int i = base + tid;
        int f = 0;
        if (i < NANCH) f = (L[i] == flagval) ? 1 : 0;
        int v = f;
        #pragma unroll
        for (int d = 1; d < 32; d <<= 1) {
            int x = __shfl_up_sync(0xFFFFFFFFu, v, d);
            if ((tid & 31) >= d) v += x;
        }
        if ((tid & 31) == 31) wsum[wid] = v;
        __syncthreads();
        if (wid == 0) {
            int w = wsum[tid & 31];
            #pragma unroll
            for (int d = 1; d < 32; d <<= 1) {
                int x = __shfl_up_sync(0xFFFFFFFFu, w, d);
                if ((tid & 31) >= d) w += x;
            }
            wsum[tid & 31] = w;
        }
        __syncthreads();
        int offset = (wid > 0) ? wsum[wid - 1] : 0;
        int incl = run + offset + v;
        if (i < NANCH && f && incl > cap) L[i] = -1;
        __syncthreads();
        if (tid == 0) run += wsum[31];
        __syncthreads();
    }
    return run;   // total flags (pre-cap); same value for all threads
}

__global__ void __launch_bounds__(1024) at3()
{
    const int b = blockIdx.x;
    int* L = g_labels + b * NANCH;
    int totfg = capped_pass(L, 1, 128);
    int fg_kept = min(totfg, 128);
    int num_bg = 256 - fg_kept;
    int totbg = capped_pass(L, 0, num_bg);
    int bg_kept = min(totbg, num_bg);
    if (threadIdx.x == 0) g_nex[b] = fg_kept + bg_kept;
}

// ---------------------------------------------------------------------------
// loss reduction. grid (67, BATCH), block 256
// ---------------------------------------------------------------------------
__global__ void loss_kernel(const float* __restrict__ gt)
{
    const int b = blockIdx.y;
    const int n = blockIdx.x * 256 + threadIdx.x;
    float np = 0.f, cn = 0.f, rs = 0.f;
    if (n < NANCH) {
        int lab = g_labels[b * NANCH + n];
        if (lab != -1) {
            int p = n / 9, a = n - 9 * p;
            float s0 = g_cls[b * 18 * HW + a * HW + p];
            float s1 = g_cls[b * 18 * HW + (9 + a) * HW + p];
            float m = fmaxf(s0, s1);
            float lse = m + logf(expf(s0 - m) + expf(s1 - m));
            float pick = ((lab == 1) ? s1 : s0) - lse;
            np = -pick; cn = 1.f;
            if (lab == 1) {
                float ax1, ay1, ax2, ay2;
                anchor_coords(n, ax1, ay1, ax2, ay2);
                int g = g_amax[b * NANCH + n];
                const float* G = gt + (b * 20 + g) * 5;
                float ew = ax2 - ax1 + 1.f, eh = ay2 - ay1 + 1.f;
                float ecx = ax1 + 0.5f * ew, ecy = ay1 + 0.5f * eh;
                float gw = G[2] - G[0] + 1.f, gh = G[3] - G[1] + 1.f;
                float gcx = G[0] + 0.5f * gw, gcy = G[1] + 0.5f * gh;
                float t0 = (gcx - ecx) / ew;
                float t1 = (gcy - ecy) / eh;
                float t2 = logf(gw / ew);
                float t3 = logf(gh / eh);
                const float* rb = g_reg + b * 36 * HW;
                float d0 = rb[(4 * a + 0) * HW + p] - t0;
                float d1 = rb[(4 * a + 1) * HW + p] - t1;
                float d2 = rb[(4 * a + 2) * HW + p] - t2;
                float d3 = rb[(4 * a + 3) * HW + p] - t3;
                rs = smooth1(d0) + smooth1(d1) + smooth1(d2) + smooth1(d3);
            }
        }
    }
    __shared__ float r0[256], r1[256], r2[256];
    const int tid = threadIdx.x;
    r0[tid] = np; r1[tid] = cn; r2[tid] = rs;
    __syncthreads();
    for (int s = 128; s > 0; s >>= 1) {
        if (tid < s) { r0[tid] += r0[tid + s]; r1[tid] += r1[tid + s]; r2[tid] += r2[tid + s]; }
        __syncthreads();
    }
    if (tid == 0) {
        atomicAdd(&g_acc[0], r0[0]);
        atomicAdd(&g_acc[1], r1[0]);
        atomicAdd(&g_acc[2 + b], r2[0]);
    }
}

__global__ void finalize(float* __restrict__ out)
{
    float cnt = fmaxf(g_acc[1], 1.f);
    out[BATCH * POST * 5 + 0] = g_acc[0] / cnt;
    float rr0 = g_acc[2] / fmaxf((float)g_nex[0], 1.f);
    float rr1 = g_acc[3] / fmaxf((float)g_nex[1], 1.f);
    out[BATCH * POST * 5 + 1] = 0.5f * (rr0 + rr1);
}

// ---------------------------------------------------------------------------
// launcher
// ---------------------------------------------------------------------------
extern "C" void kernel_launch(void* const* d_in, const int* in_sizes, int n_in,
                              void* d_out, int out_size)
{
    const float* feature = (const float*)d_in[0];
    const float* gt      = (const float*)d_in[1];
    const float* iminfo  = (const float*)d_in[2];
    const float* wconv   = (const float*)d_in[3];
    const float* bconv   = (const float*)d_in[4];
    const float* wcls    = (const float*)d_in[5];
    const float* bcls    = (const float*)d_in[6];
    const float* wreg    = (const float*)d_in[7];
    const float* breg    = (const float*)d_in[8];
    float* out = (float*)d_out;

    cudaFuncSetAttribute(conv3_gemm, cudaFuncAttributeMaxDynamicSharedMemorySize, C3_SMEM_BYTES);
    cudaFuncSetAttribute(conv1x1, cudaFuncAttributeMaxDynamicSharedMemorySize, C1_SMEM_BYTES);
    cudaFuncSetAttribute(select_sort, cudaFuncAttributeMaxDynamicSharedMemorySize, 65536);

    init_zero<<<1, 64>>>();
    conv3_gemm<<<dim3(15, 4, BATCH), 512, C3_SMEM_BYTES>>>(feature, wconv, bconv);
    conv1x1<<<dim3(60, BATCH), 256, C1_SMEM_BYTES>>>(wcls, bcls, wreg, breg);
    proposal_prep<<<dim3(67, BATCH), 256>>>(iminfo);
    select_sort<<<BATCH, 1024, 65536>>>();
    nms_mask_k<<<dim3(NW, NW, BATCH), 64>>>();
    nms_scan<<<BATCH, 32>>>(out);
    at1<<<dim3(67, BATCH), 256>>>(gt, iminfo);
    at2<<<dim3(67, BATCH), 256>>>(gt, iminfo);
    at3<<<BATCH, 1024>>>();
    loss_kernel<<<dim3(67, BATCH), 256>>>(gt);
    finalize<<<1, 1>>>(out);
}

// round 13
// speedup vs baseline: 1.1860x; 1.0238x over previous
#include <cuda_runtime.h>
#include <cuda_bf16.h>

// ---------------------------------------------------------------------------
// Problem constants
// ---------------------------------------------------------------------------
#define BATCH   2
#define HF      38
#define WF      50
#define HW      1900          // HF*WF
#define ANUM    9
#define NANCH   17100         // HW*ANUM
#define CIN     1024
#define CMID    512
#define K9      9216          // CIN*9
#define KT      64
#define NKT     (K9 / KT)     // 144
#define AP      132           // padded A width (4-way instead of 32-way STS conflict)
#define PRE     6000
#define POST    300
#define NW      94            // ceil(PRE/64)
#define NMS_TH  0.7f
#define SCHUNK  64
#define NCHUNK  ((PRE + SCHUNK - 1) / SCHUNK)   // 94

// canonical Faster-RCNN base anchors (base=16, ratios .5/1/2, scales 8/16/32)
__constant__ float c_base[9][4] = {
    {-84.f,  -40.f,  99.f,  55.f},
    {-176.f, -88.f, 191.f, 103.f},
    {-360.f,-184.f, 375.f, 199.f},
    {-56.f,  -56.f,  71.f,  71.f},
    {-120.f,-120.f, 135.f, 135.f},
    {-248.f,-248.f, 263.f, 263.f},
    {-36.f,  -80.f,  51.f,  95.f},
    {-80.f, -168.f,  95.f, 183.f},
    {-168.f,-344.f, 183.f, 359.f}
};

// ---------------------------------------------------------------------------
// Scratch (static device allocations; runtime alloc is forbidden)
// ---------------------------------------------------------------------------
__device__ float               g_x    [BATCH * CMID * HW];   // conv3+relu out
__device__ float               g_cls  [BATCH * 18 * HW];
__device__ float               g_reg  [BATCH * 36 * HW];
__device__ unsigned long long  g_keys [BATCH * NANCH];
__device__ float               g_boxes[BATCH * NANCH * 4];
__device__ float               g_tops [BATCH * PRE * 4];
__device__ unsigned long long  g_mask [BATCH * PRE * NW];
__device__ int                 g_labels[BATCH * NANCH];
__device__ int                 g_amax [BATCH * NANCH];
__device__ unsigned int        g_gtmax[BATCH * 20];
__device__ float               g_acc  [4];                   // negpick, cnt, reg0, reg1
__device__ int                 g_nex  [BATCH];

// ---------------------------------------------------------------------------
// helpers
// ---------------------------------------------------------------------------
__device__ __forceinline__ unsigned f2u(float f) {
    unsigned u = __float_as_uint(f);
    return (u & 0x80000000u) ? ~u : (u | 0x80000000u);
}
__device__ __forceinline__ float u2f(unsigned u) {
    unsigned bits = (u & 0x80000000u) ? (u & 0x7FFFFFFFu) : ~u;
    return __uint_as_float(bits);
}
__device__ __forceinline__ void anchor_coords(int n, float& ax1, float& ay1,
                                              float& ax2, float& ay2) {
    int p = n / 9, a = n - 9 * p;
    int y = p / WF, x = p - WF * y;
    float sx = 16.f * x, sy = 16.f * y;
    ax1 = c_base[a][0] + sx; ay1 = c_base[a][1] + sy;
    ax2 = c_base[a][2] + sx; ay2 = c_base[a][3] + sy;
}
__device__ __forceinline__ float smooth1(float d) {
    float ad = fabsf(d);
    return (ad < (1.0f / 9.0f)) ? (4.5f * d * d) : (ad - 0.5f / 9.0f);
}

// packed f32x2 ops (bit-identical to two independent scalar IEEE ops)
typedef unsigned long long ull;
#define SGN2 0x8000000080000000ULL
__device__ __forceinline__ ull dup2(float s) {
    ull d; asm("mov.b64 %0, {%1, %1};" : "=l"(d) : "f"(s)); return d;
}
__device__ __forceinline__ ull fma2(ull a, ull b, ull c) {
    ull d; asm("fma.rn.f32x2 %0, %1, %2, %3;" : "=l"(d) : "l"(a), "l"(b), "l"(c));
    return d;
}
__device__ __forceinline__ ull add2(ull a, ull b) {
    ull d; asm("add.rn.f32x2 %0, %1, %2;" : "=l"(d) : "l"(a), "l"(b)); return d;
}
__device__ __forceinline__ ull sub2(ull a, ull b) {   // a + (-b), same rounding as scalar sub
    return add2(a, b ^ SGN2);
}
__device__ __forceinline__ void unpack2(ull v, float& lo, float& hi) {
    asm("mov.b64 {%0, %1}, %2;" : "=f"(lo), "=f"(hi) : "l"(v));
}

// cp.async helpers
__device__ __forceinline__ void cpa4(unsigned dst, const void* src, int srcsz) {
    asm volatile("cp.async.ca.shared.global [%0], [%1], 4, %2;"
                 :: "r"(dst), "l"(src), "r"(srcsz));
}
__device__ __forceinline__ void cpa16(unsigned dst, const void* src) {
    asm volatile("cp.async.cg.shared.global [%0], [%1], 16;"
                 :: "r"(dst), "l"(src));
}
#define CP_COMMIT()   asm volatile("cp.async.commit_group;")
#define CP_WAIT(n)    asm volatile("cp.async.wait_group %0;" :: "n"(n))
#define CP_WAIT_ALL() asm volatile("cp.async.wait_all;")

// ---------------------------------------------------------------------------
// zero-init kernel (accumulators)
// ---------------------------------------------------------------------------
__global__ void init_zero() {
    int t = threadIdx.x;
    if (t < 4)  g_acc[t] = 0.f;
    if (t < BATCH * 20) g_gtmax[t] = 0u;
}

// ---------------------------------------------------------------------------
// conv3x3 1024->512 as implicit-GEMM, 128x128 tiles, KT=64, f32x2 packed FMA,
// Kahan-compensated per-tile merge, cp.async DOUBLE-BUFFERED pipeline.
// grid (15, 4, BATCH), block 512, micro-tile 8(m, 4 pairs) x 4(n).
// dyn smem: 2 x A[KT][AP] + 2 x B[KT][128] = 133120 B.  (exact R8 config)
// ---------------------------------------------------------------------------
extern __shared__ unsigned char smem_raw[];

#define C3_A_FLOATS (KT * AP)     // 8448
#define C3_B_FLOATS (KT * 128)    // 8192
#define C3_SMEM_BYTES ((2 * C3_A_FLOATS + 2 * C3_B_FLOATS) * 4)  // 133120

__global__ void __launch_bounds__(512) conv3_gemm(
    const float* __restrict__ feat, const float* __restrict__ wconv,
    const float* __restrict__ bconv)
{
    float* AsBuf = (float*)smem_raw;                 // [2][KT][AP]
    float* BsBuf = AsBuf + 2 * C3_A_FLOATS;          // [2][KT][128]
    const unsigned sA = (unsigned)__cvta_generic_to_shared(AsBuf);
    const unsigned sB = (unsigned)__cvta_generic_to_shared(BsBuf);

    const int b  = blockIdx.z;
    const int m0 = blockIdx.y * 128;
    const int n0 = blockIdx.x * 128;
    const int tid = threadIdx.x;

    ull acc2[16], comp2[16];
    #pragma unroll
    for (int e = 0; e < 16; e++) { acc2[e] = 0ULL; comp2[e] = 0ULL; }

    const int bcol = tid & 127;
    const int p    = n0 + bcol;
    const int py   = p / WF, px = p - WF * (p / WF);
    const bool pvalid = p < HW;
    const float* fb = feat + b * (CIN * HW);

    const int tm = (tid >> 5) << 3;   // warp-uniform: 0..120
    const int tn = (tid & 31) << 2;   // 0..124
    const int krow0 = tid >> 7;       // 0..3

    auto issue_tile = [&](int kt, int buf) {
        // A tile: 128 m x 64 k = 8192 elems, 16 x cp.async 4B per thread
        #pragma unroll
        for (int r = 0; r < 16; r++) {
            int e = tid + 512 * r;
            int row = e >> 6, col = e & 63;
            const float* src = &wconv[(m0 + row) * K9 + kt * KT + col];
            unsigned dst = sA + (unsigned)((buf * KT + col) * AP + row) * 4u;
            cpa4(dst, src, 4);
        }
        // B tile (im2col): 64 k-rows x 128 cols, 16 x cp.async 4B,
        // zero-fill when out of bounds
        #pragma unroll
        for (int r = 0; r < 16; r++) {
            int krow = krow0 + 4 * r;
            int kg = kt * KT + krow;
            int c = kg / 9;
            int t = kg - 9 * c;
            int dy = t / 3 - 1;
            int dx = t - (t / 3) * 3 - 1;
            int yy = py + dy, xx = px + dx;
            bool valid = pvalid && (unsigned)yy < (unsigned)HF && (unsigned)xx < (unsigned)WF;
            const float* src = valid ? &fb[c * HW + yy * WF + xx] : fb;
            unsigned dst = sB + (unsigned)((buf * KT + krow) * 128 + bcol) * 4u;
            cpa4(dst, src, valid ? 4 : 0);
        }
        CP_COMMIT();
    };

    issue_tile(0, 0);
    CP_WAIT(0);
    __syncthreads();

    for (int kt = 0; kt < NKT; kt++) {
        const int cur = kt & 1;
        if (kt + 1 < NKT) issue_tile(kt + 1, cur ^ 1);

        const float* As_cur = AsBuf + cur * C3_A_FLOATS;
        const float* Bs_cur = BsBuf + cur * C3_B_FLOATS;

        ull part2[16];
        #pragma unroll
        for (int e = 0; e < 16; e++) part2[e] = 0ULL;

        #pragma unroll 8
        for (int kk = 0; kk < KT; kk++) {
            const ulonglong2* ap = (const ulonglong2*)&As_cur[kk * AP + tm];
            ulonglong2 a01 = ap[0];
            ulonglong2 a23 = ap[1];
            ull am[4] = {a01.x, a01.y, a23.x, a23.y};
            float4 bq = *(const float4*)&Bs_cur[kk * 128 + tn];
            ull bd[4] = {dup2(bq.x), dup2(bq.y), dup2(bq.z), dup2(bq.w)};
            #pragma unroll
            for (int mp = 0; mp < 4; mp++)
                #pragma unroll
                for (int j = 0; j < 4; j++)
                    part2[mp * 4 + j] = fma2(am[mp], bd[j], part2[mp * 4 + j]);
        }
        // Kahan merge of the 64-product partial into the running sum (f32x2)
        #pragma unroll
        for (int e = 0; e < 16; e++) {
            ull y = sub2(part2[e], comp2[e]);
            ull t = add2(acc2[e], y);
            comp2[e] = sub2(sub2(t, acc2[e]), y);
            acc2[e] = t;
        }
        if (kt + 1 < NKT) CP_WAIT(0);
        __syncthreads();
    }
    #pragma unroll
    for (int mp = 0; mp < 4; mp++) {
        int co0 = m0 + tm + 2 * mp;
        float b0 = bconv[co0], b1 = bconv[co0 + 1];
        #pragma unroll
        for (int j = 0; j < 4; j++) {
            int pp = n0 + tn + j;
            if (pp < HW) {
                float lo, hi;
                unpack2(acc2[mp * 4 + j], lo, hi);
                float v0 = lo + b0, v1 = hi + b1;
                g_x[b * (CMID * HW) + co0 * HW + pp]       = v0 > 0.f ? v0 : 0.f;
                g_x[b * (CMID * HW) + (co0 + 1) * HW + pp] = v1 > 0.f ? v1 : 0.f;
            }
        }
    }
}

// ---------------------------------------------------------------------------
// fused 1x1 convs (cls 18 + reg 36), Kahan accumulation, 8-way K-split.
// grid (60, BATCH), block 256 = 32 positions x 8 K-chunks of 64 channels.
// ALL in dynamic smem: wT [512][54] (110592 B) + partials [32][54][8]
// (55296 B) = 165888 B. Deterministic fixed-order merge (no float atomics).
// ---------------------------------------------------------------------------
#define C1_POS 32
#define C1_KS  8
#define C1_WT_FLOATS (512 * 54)
#define C1_SMEM_BYTES ((C1_WT_FLOATS + C1_POS * 54 * C1_KS) * 4)

__global__ void __launch_bounds__(256) conv1x1(
    const float* __restrict__ wcls, const float* __restrict__ bcls,
    const float* __restrict__ wreg, const float* __restrict__ breg)
{
    float* wT = (float*)smem_raw;                 // [512][54]
    float* sp = wT + C1_WT_FLOATS;                // [32][54][8]
    const int b  = blockIdx.y;
    const int p0 = blockIdx.x * C1_POS;
    const int tid = threadIdx.x;
    const int pos = tid & 31;
    const int ks  = tid >> 5;      // 0..7

    for (int e = tid; e < 512 * 18; e += 256) {
        int o = e / 512, c = e - 512 * o;
        wT[c * 54 + o] = wcls[e];
    }
    for (int e = tid; e < 512 * 36; e += 256) {
        int o = e / 512, c = e - 512 * o;
        wT[c * 54 + 18 + o] = wreg[e];
    }
    __syncthreads();

    const int p = p0 + pos;
    const bool v = p < HW;
    float acc[54], comp[54];
    #pragma unroll
    for (int o = 0; o < 54; o++) { acc[o] = 0.f; comp[o] = 0.f; }

    const float* xb = g_x + b * (CMID * HW) + (v ? p : 0);
    const int c0 = ks * 64;
    for (int c = c0; c < c0 + 64; c++) {
        float xv = v ? xb[c * HW] : 0.f;
        const float* w = &wT[c * 54];
        #pragma unroll
        for (int o = 0; o < 54; o++) {
            float y = __fmaf_rn(xv, w[o], -comp[o]);
            float t = __fadd_rn(acc[o], y);
            comp[o] = __fsub_rn(__fsub_rn(t, acc[o]), y);
            acc[o] = t;
        }
    }
    #pragma unroll
    for (int o = 0; o < 54; o++) sp[(pos * 54 + o) * C1_KS + ks] = acc[o];
    __syncthreads();

    // merge 8 partials per (pos, o) in fixed order -> deterministic
    for (int e = tid; e < C1_POS * 54; e += 256) {
        int pos2 = e / 54, o = e - 54 * pos2;
        int pp = p0 + pos2;
        if (pp >= HW) continue;
        float s = 0.f;
        #pragma unroll
        for (int k = 0; k < C1_KS; k++) s = __fadd_rn(s, sp[(pos2 * 54 + o) * C1_KS + k]);
        if (o < 18) g_cls[b * 18 * HW + o * HW + pp] = s + bcls[o];
        else        g_reg[b * 36 * HW + (o - 18) * HW + pp] = s + breg[o - 18];
    }
}

// ---------------------------------------------------------------------------
// proposal prep: decode boxes, clip, filter, build sort keys
// grid (67, BATCH), block 256
// ---------------------------------------------------------------------------
__global__ void proposal_prep(const float* __restrict__ iminfo)
{
    const int b = blockIdx.y;
    const int n = blockIdx.x * 256 + threadIdx.x;
    if (n >= NANCH) return;
    const int p = n / 9, a = n - 9 * p;

    float ax1, ay1, ax2, ay2;
    anchor_coords(n, ax1, ay1, ax2, ay2);

    const float* rb = g_reg + b * 36 * HW;
    float d0 = rb[(4 * a + 0) * HW + p];
    float d1 = rb[(4 * a + 1) * HW + p];
    float d2 = rb[(4 * a + 2) * HW + p];
    float d3 = rb[(4 * a + 3) * HW + p];

    float w  = ax2 - ax1 + 1.f, h = ay2 - ay1 + 1.f;
    float cx = ax1 + 0.5f * w,  cy = ay1 + 0.5f * h;
    float pcx = d0 * w + cx, pcy = d1 * h + cy;
    float pw = expf(d2) * w, ph = expf(d3) * h;

    float imh = iminfo[b * 3 + 0] - 1.f;
    float imw = iminfo[b * 3 + 1] - 1.f;
    float sc  = iminfo[b * 3 + 2];

    float x1 = fminf(fmaxf(pcx - 0.5f * pw, 0.f), imw);
    float y1 = fminf(fmaxf(pcy - 0.5f * ph, 0.f), imh);
    float x2 = fminf(fmaxf(pcx + 0.5f * pw, 0.f), imw);
    float y2 = fminf(fmaxf(pcy + 0.5f * ph, 0.f), imh);

    bool valid = (x2 - x1 + 1.f >= 16.f * sc) && (y2 - y1 + 1.f >= 16.f * sc);

    float s0 = g_cls[b * 18 * HW + a * HW + p];
    float s1 = g_cls[b * 18 * HW + (9 + a) * HW + p];
    float m  = fmaxf(s0, s1);
    float e0 = expf(s0 - m), e1 = expf(s1 - m);
    float sco = e1 / (e0 + e1);
    if (!valid) sco = -1e9f;

    g_keys[b * NANCH + n] =
        ((unsigned long long)(~f2u(sco)) << 32) | (unsigned)n;
    float4 bx = make_float4(x1, y1, x2, y2);
    ((float4*)g_boxes)[b * NANCH + n] = bx;
}

// ---------------------------------------------------------------------------
// radix-select rank 5999 + compact + bitonic sort 8192 in smem
// grid BATCH, block 1024, dyn smem 65536
// ---------------------------------------------------------------------------
__global__ void __launch_bounds__(1024) select_sort()
{
    unsigned long long* sb = (unsigned long long*)smem_raw;  // 8192 keys
    __shared__ unsigned int hist[256];
    __shared__ unsigned int pref[256];
    __shared__ unsigned long long s_cur;
    __shared__ int s_target;
    __shared__ int s_cnt;

    const int b = blockIdx.x;
    const int tid = threadIdx.x;
    const unsigned long long* kb = g_keys + b * NANCH;

    if (tid == 0) { s_cur = 0ull; s_target = PRE - 1; }
    __syncthreads();

    for (int pass = 0; pass < 8; pass++) {
        int shift = 56 - 8 * pass;
        if (tid < 256) hist[tid] = 0;
        __syncthreads();
        unsigned long long cur  = s_cur;
        unsigned long long mask = pass ? (~0ull << (64 - 8 * pass)) : 0ull;
        for (int i = tid; i < NANCH; i += 1024) {
            unsigned long long k = kb[i];
            if ((k & mask) == cur)
                atomicAdd(&hist[(unsigned)((k >> shift) & 255ull)], 1u);
        }
        __syncthreads();
        // parallel inclusive prefix over 256 buckets (Hillis-Steele)
        if (tid < 256) pref[tid] = hist[tid];
        __syncthreads();
        #pragma unroll
        for (int d = 1; d < 256; d <<= 1) {
            unsigned v = 0;
            if (tid < 256 && tid >= d) v = pref[tid - d];
            __syncthreads();
            if (tid < 256) pref[tid] += v;
            __syncthreads();
        }
        int tgt = s_target;
        __syncthreads();
        if (tid < 256) {
            unsigned incl = pref[tid];
            unsigned cnt  = hist[tid];
            unsigned excl = incl - cnt;
            if (cnt > 0 && (unsigned)tgt >= excl && (unsigned)tgt < incl) {
                s_cur = cur | ((unsigned long long)tid << shift);
                s_target = tgt - (int)excl;
            }
        }
        __syncthreads();
    }
    unsigned long long T = s_cur;

    for (int i = tid; i < 8192; i += 1024) sb[i] = ~0ull;
    if (tid == 0) s_cnt = 0;
    __syncthreads();
    for (int i = tid; i < NANCH; i += 1024) {
        unsigned long long k = kb[i];
        if (k <= T) { int pos = atomicAdd(&s_cnt, 1); sb[pos] = k; }
    }
    __syncthreads();

    for (int k2 = 2; k2 <= 8192; k2 <<= 1)
        for (int j = k2 >> 1; j > 0; j >>= 1) {
            for (int i = tid; i < 8192; i += 1024) {
                int ixj = i ^ j;
                if (ixj > i) {
                    unsigned long long a = sb[i], c = sb[ixj];
                    bool up = ((i & k2) == 0);
                    if ((a > c) == up) { sb[i] = c; sb[ixj] = a; }
                }
            }
            __syncthreads();
        }

    const float4* bb = (const float4*)(g_boxes) + b * NANCH;
    float4* tb = (float4*)(g_tops) + b * PRE;
    for (int r = tid; r < PRE; r += 1024) {
        int n = (int)(sb[r] & 0xFFFFFFFFull);
        tb[r] = bb[n];
    }
}

// ---------------------------------------------------------------------------
// NMS suppression bitmask. grid (NW, NW, BATCH), block 64
// ---------------------------------------------------------------------------
__global__ void nms_mask_k()
{
    const int b = blockIdx.z, rb = blockIdx.y, cb = blockIdx.x;
    const float4* tb = (const float4*)(g_tops) + b * PRE;
    __shared__ float4 cbox[64];
    const int t = threadIdx.x;
    const int j0 = cb * 64;
    const int jn = min(64, PRE - j0);
    if (t < jn) cbox[t] = tb[j0 + t];
    __syncthreads();
    const int i = rb * 64 + t;
    if (i >= PRE) return;
    float4 bi = tb[i];
    float areai = (bi.z - bi.x + 1.f) * (bi.w - bi.y + 1.f);
    unsigned long long m = 0ull;
    for (int jj = 0; jj < jn; jj++) {
        int j = j0 + jj;
        if (j <= i) continue;
        float4 bj = cbox[jj];
        float iw = fminf(bi.z, bj.z) - fmaxf(bi.x, bj.x) + 1.f;
        float ih = fminf(bi.w, bj.w) - fmaxf(bi.y, bj.y) + 1.f;
        if (iw > 0.f && ih > 0.f) {
            float inter = iw * ih;
            float aj = (bj.z - bj.x + 1.f) * (bj.w - bj.y + 1.f);
            float iou = inter / (areai + aj - inter);
            if (iou > NMS_TH) m |= (1ull << jj);
        }
    }
    g_mask[(b * PRE + i) * NW + cb] = m;
}

// ---------------------------------------------------------------------------
// serial keep scan (one warp per batch), CHUNKED double-buffered SMEM scan:
// 64 mask rows per cp.async commit group, per-row work is pure SMEM
// (no per-row waits). Keep semantics identical to the row-by-row version.
// dyn smem: 2 x SCHUNK x NW ull = 96256 B.
// ---------------------------------------------------------------------------
__global__ void nms_scan(float* __restrict__ out)
{
    const int b = blockIdx.x;
    const int lane = threadIdx.x;  // 32 threads
    __shared__ unsigned long long rem[NW];
    __shared__ int keep[POST];
    ull* buf = (ull*)smem_raw;     // [2][SCHUNK][NW]
    for (int i = lane; i < NW; i += 32) rem[i] = 0ull;

    const unsigned bufaddr = (unsigned)__cvta_generic_to_shared(buf);
    const char* mbase = (const char*)g_mask + (size_t)b * PRE * NW * 8;

    auto prefetch = [&](int q, int slot) {
        int r0 = q * SCHUNK;
        int rows = min(SCHUNK, PRE - r0);
        int w16 = rows * 47;                 // 47 x 16B per row (NW*8=752 B)
        for (int w = lane; w < w16; w += 32) {
            int r = w / 47, c = w - 47 * r;
            cpa16(bufaddr + (unsigned)((slot * SCHUNK + r) * NW * 8 + c * 16),
                  mbase + (size_t)(r0 + r) * NW * 8 + c * 16);
        }
        CP_COMMIT();
    };

    prefetch(0, 0);
    int cnt = 0;
    for (int q = 0; q < NCHUNK && cnt < POST; q++) {
        const int slot = q & 1;
        const bool more = (q + 1 < NCHUNK);
        if (more) { prefetch(q + 1, slot ^ 1); CP_WAIT(1); }
        else      { CP_WAIT(0); }
        __syncwarp();

        const int r0 = q * SCHUNK;
        const int rows = min(SCHUNK, PRE - r0);
        for (int r = 0; r < rows && cnt < POST; r++) {
            int i = r0 + r;
            bool alive = !((rem[i >> 6] >> (i & 63)) & 1ull);
            if (alive) {
                const ull* mr = buf + (size_t)(slot * SCHUNK + r) * NW;
                rem[lane]      |= mr[lane];
                rem[lane + 32] |= mr[lane + 32];
                if (lane + 64 < NW) rem[lane + 64] |= mr[lane + 64];
                if (lane == 0) keep[cnt] = i;
                cnt++;
                __syncwarp();
            }
        }
    }
    CP_WAIT_ALL();
    __syncwarp();

    const float4* tb = (const float4*)(g_tops) + b * PRE;
    for (int k = lane; k < POST; k += 32) {
        int sel = (k < cnt) ? keep[k] : 0;   // jnp.nonzero fill_value=0
        float4 v = tb[sel];
        float* o = out + (size_t)(b * POST + k) * 5;
        o[0] = (float)b; o[1] = v.x; o[2] = v.y; o[3] = v.z; o[4] = v.w;
    }
}

#define NS_SMEM_BYTES (2 * SCHUNK * NW * 8)   // 96256

// ---------------------------------------------------------------------------
// anchor target pass 1: per-gt max IoU only (no g_ov materialization).
// grid (67, BATCH), block 256
// ---------------------------------------------------------------------------
__global__ void at1(const float* __restrict__ gt, const float* __restrict__ iminfo)
{
    const int b = blockIdx.y;
    const int n = blockIdx.x * 256 + threadIdx.x;
    const int t = threadIdx.x;
    __shared__ float4 sgt[20];
    __shared__ unsigned int smax[20];
    if (t < 20) {
        const float* g = gt + (b * 20 + t) * 5;
        sgt[t] = make_float4(g[0], g[1], g[2], g[3]);
        smax[t] = 0u;
    }
    __syncthreads();

    if (n < NANCH) {
        float ax1, ay1, ax2, ay2;
        anchor_coords(n, ax1, ay1, ax2, ay2);
        bool inside = (ax1 >= 0.f) && (ay1 >= 0.f) &&
                      (ax2 < iminfo[b * 3 + 1]) && (ay2 < iminfo[b * 3 + 0]);
        float areaa = (ax2 - ax1 + 1.f) * (ay2 - ay1 + 1.f);
        #pragma unroll
        for (int g = 0; g < 20; g++) {
            float4 G = sgt[g];
            float iw = fmaxf(fminf(ax2, G.z) - fmaxf(ax1, G.x) + 1.f, 0.f);
            float ih = fmaxf(fminf(ay2, G.w) - fmaxf(ay1, G.y) + 1.f, 0.f);
            float inter = iw * ih;
            float areab = (G.z - G.x + 1.f) * (G.w - G.y + 1.f);
            float o = inter / (areaa + areab - inter);
            if (!inside) o = -1.f;
            atomicMax(&smax[g], f2u(o));
        }
    }
    __syncthreads();
    if (t < 20) atomicMax(&g_gtmax[b * 20 + t], smax[t]);
}

// anchor target pass 2: labels from RECOMPUTED IoUs (identical formula on
// identical inputs -> identical values to pass 1). grid (67, BATCH), block 256
__global__ void at2(const float* __restrict__ gt, const float* __restrict__ iminfo)
{
    const int b = blockIdx.y;
    const int n = blockIdx.x * 256 + threadIdx.x;
    const int t = threadIdx.x;
    __shared__ float4 sgt[20];
    __shared__ float sgm[20];
    if (t < 20) {
        const float* g = gt + (b * 20 + t) * 5;
        sgt[t] = make_float4(g[0], g[1], g[2], g[3]);
        sgm[t] = u2f(g_gtmax[b * 20 + t]);
    }
    __syncthreads();
    if (n >= NANCH) return;

    float ax1, ay1, ax2, ay2;
    anchor_coords(n, ax1, ay1, ax2, ay2);
    bool inside = (ax1 >= 0.f) && (ay1 >= 0.f) &&
                  (ax2 < iminfo[b * 3 + 1]) && (ay2 < iminfo[b * 3 + 0]);
    float areaa = (ax2 - ax1 + 1.f) * (ay2 - ay1 + 1.f);

    float mo = -2.f; int am = 0; bool isg = false;
    #pragma unroll
    for (int g = 0; g < 20; g++) {
        float4 G = sgt[g];
        float iw = fmaxf(fminf(ax2, G.z) - fmaxf(ax1, G.x) + 1.f, 0.f);
        float ih = fmaxf(fminf(ay2, G.w) - fmaxf(ay1, G.y) + 1.f, 0.f);
        float inter = iw * ih;
        float areab = (G.z - G.x + 1.f) * (G.w - G.y + 1.f);
        float v = inter / (areaa + areab - inter);
        if (!inside) v = -1.f;
        if (v > mo) { mo = v; am = g; }
        if (v == sgm[g] && sgm[g] > 0.f) isg = true;
    }
    int lab = -1;
    if (inside && mo < 0.3f) lab = 0;
    if (inside && isg)       lab = 1;
    if (inside && mo >= 0.7f) lab = 1;
    g_labels[b * NANCH + n] = lab;
    g_amax  [b * NANCH + n] = am;
}

// sequential cumsum caps (single block per batch, 1024 threads)
__device__ int capped_pass(int* L, int flagval, int cap)
{
    __shared__ int wsum[32];
    __shared__ int run;
    const int tid = threadIdx.x;
    const int wid = tid >> 5;
    if (tid == 0) run = 0;
    __syncthreads();
    for (int base = 0; base < NANCH; base += 1024) {
        int i = base + tid;
        int f = 0;
        if (i < NANCH) f = (L[i] == flagval) ? 1 : 0;
        int v = f;
        #pragma unroll
        for (int d = 1; d < 32; d <<= 1) {
            int x = __shfl_up_sync(0xFFFFFFFFu, v, d);
            if ((tid & 31) >= d) v += x;
        }
        if ((tid & 31) == 31) wsum[wid] = v;
        __syncthreads();
        if (wid == 0) {
            int w = wsum[tid & 31];
            #pragma unroll
            for (int d = 1; d < 32; d <<= 1) {
                int x = __shfl_up_sync(0xFFFFFFFFu, w, d);
                if ((tid & 31) >= d) w += x;
            }
            wsum[tid & 31] = w;
        }
        __syncthreads();
        int offset = (wid > 0) ? wsum[wid - 1] : 0;
        int incl = run + offset + v;
        if (i < NANCH && f && incl > cap) L[i] = -1;
        __syncthreads();
        if (tid == 0) run += wsum[31];
        __syncthreads();
    }
    return run;   // total flags (pre-cap); same value for all threads
}

__global__ void __launch_bounds__(1024) at3()
{
    const int b = blockIdx.x;
    int* L = g_labels + b * NANCH;
    int totfg = capped_pass(L, 1, 128);
    int fg_kept = min(totfg, 128);
    int num_bg = 256 - fg_kept;
    int totbg = capped_pass(L, 0, num_bg);
    int bg_kept = min(totbg, num_bg);
    if (threadIdx.x == 0) g_nex[b] = fg_kept + bg_kept;
}

// ---------------------------------------------------------------------------
// loss reduction. grid (67, BATCH), block 256
// ---------------------------------------------------------------------------
__global__ void loss_kernel(const float* __restrict__ gt)
{
    const int b = blockIdx.y;
    const int n = blockIdx.x * 256 + threadIdx.x;
    float np = 0.f, cn = 0.f, rs = 0.f;
    if (n < NANCH) {
        int lab = g_labels[b * NANCH + n];
        if (lab != -1) {
            int p = n / 9, a = n - 9 * p;
            float s0 = g_cls[b * 18 * HW + a * HW + p];
            float s1 = g_cls[b * 18 * HW + (9 + a) * HW + p];
            float m = fmaxf(s0, s1);
            float lse = m + logf(expf(s0 - m) + expf(s1 - m));
            float pick = ((lab == 1) ? s1 : s0) - lse;
            np = -pick; cn = 1.f;
            if (lab == 1) {
                float ax1, ay1, ax2, ay2;
                anchor_coords(n, ax1, ay1, ax2, ay2);
                int g = g_amax[b * NANCH + n];
                const float* G = gt + (b * 20 + g) * 5;
                float ew = ax2 - ax1 + 1.f, eh = ay2 - ay1 + 1.f;
                float ecx = ax1 + 0.5f * ew, ecy = ay1 + 0.5f * eh;
                float gw = G[2] - G[0] + 1.f, gh = G[3] - G[1] + 1.f;
                float gcx = G[0] + 0.5f * gw, gcy = G[1] + 0.5f * gh;
                float t0 = (gcx - ecx) / ew;
                float t1 = (gcy - ecy) / eh;
                float t2 = logf(gw / ew);
                float t3 = logf(gh / eh);
                const float* rb = g_reg + b * 36 * HW;
                float d0 = rb[(4 * a + 0) * HW + p] - t0;
                float d1 = rb[(4 * a + 1) * HW + p] - t1;
                float d2 = rb[(4 * a + 2) * HW + p] - t2;
                float d3 = rb[(4 * a + 3) * HW + p] - t3;
                rs = smooth1(d0) + smooth1(d1) + smooth1(d2) + smooth1(d3);
            }
        }
    }
    __shared__ float r0[256], r1[256], r2[256];
    const int tid = threadIdx.x;
    r0[tid] = np; r1[tid] = cn; r2[tid] = rs;
    __syncthreads();
    for (int s = 128; s > 0; s >>= 1) {
        if (tid < s) { r0[tid] += r0[tid + s]; r1[tid] += r1[tid + s]; r2[tid] += r2[tid + s]; }
        __syncthreads();
    }
    if (tid == 0) {
        atomicAdd(&g_acc[0], r0[0]);
        atomicAdd(&g_acc[1], r1[0]);
        atomicAdd(&g_acc[2 + b], r2[0]);
    }
}

__global__ void finalize(float* __restrict__ out)
{
    float cnt = fmaxf(g_acc[1], 1.f);
    out[BATCH * POST * 5 + 0] = g_acc[0] / cnt;
    float rr0 = g_acc[2] / fmaxf((float)g_nex[0], 1.f);
    float rr1 = g_acc[3] / fmaxf((float)g_nex[1], 1.f);
    out[BATCH * POST * 5 + 1] = 0.5f * (rr0 + rr1);
}

// ---------------------------------------------------------------------------
// launcher
// ---------------------------------------------------------------------------
extern "C" void kernel_launch(void* const* d_in, const int* in_sizes, int n_in,
                              void* d_out, int out_size)
{
    const float* feature = (const float*)d_in[0];
    const float* gt      = (const float*)d_in[1];
    const float* iminfo  = (const float*)d_in[2];
    const float* wconv   = (const float*)d_in[3];
    const float* bconv   = (const float*)d_in[4];
    const float* wcls    = (const float*)d_in[5];
    const float* bcls    = (const float*)d_in[6];
    const float* wreg    = (const float*)d_in[7];
    const float* breg    = (const float*)d_in[8];
    float* out = (float*)d_out;

    cudaFuncSetAttribute(conv3_gemm, cudaFuncAttributeMaxDynamicSharedMemorySize, C3_SMEM_BYTES);
    cudaFuncSetAttribute(conv1x1, cudaFuncAttributeMaxDynamicSharedMemorySize, C1_SMEM_BYTES);
    cudaFuncSetAttribute(select_sort, cudaFuncAttributeMaxDynamicSharedMemorySize, 65536);
    cudaFuncSetAttribute(nms_scan, cudaFuncAttributeMaxDynamicSharedMemorySize, NS_SMEM_BYTES);

    init_zero<<<1, 64>>>();
    conv3_gemm<<<dim3(15, 4, BATCH), 512, C3_SMEM_BYTES>>>(feature, wconv, bconv);
    conv1x1<<<dim3(60, BATCH), 256, C1_SMEM_BYTES>>>(wcls, bcls, wreg, breg);
    proposal_prep<<<dim3(67, BATCH), 256>>>(iminfo);
    select_sort<<<BATCH, 1024, 65536>>>();
    nms_mask_k<<<dim3(NW, NW, BATCH), 64>>>();
    nms_scan<<<BATCH, 32, NS_SMEM_BYTES>>>(out);
    at1<<<dim3(67, BATCH), 256>>>(gt, iminfo);
    at2<<<dim3(67, BATCH), 256>>>(gt, iminfo);
    at3<<<BATCH, 1024>>>();
    loss_kernel<<<dim3(67, BATCH), 256>>>(gt);
    finalize<<<1, 1>>>(out);
}